// round 13
// baseline (speedup 1.0000x reference)
#include <cuda_runtime.h>
#include <cuda_bf16.h>
#include <cstdint>

// LSTM  B=64, T=1024, D=512, U=512, OUT=4
#define BATCH    64
#define TSTEPS   1024
#define DIN      512
#define UNITS    512
#define FOURU    2048
#define NCTA     128
#define TPB      256
#define NBG      4
#define GROUP_CTAS 32
#define NMTILE   4096
#define NKSTEP   32

// recurrence smem offsets (bytes)
#define SM_BHI   0            // bf16 [64 n][520]     : 66560
#define SM_BLO   66560        // bf16 [64 n][520]     : 66560
#define SM_Z     133120       // f32  [2][16 b][68]   : 8704
#define SM_XZ    141824       // f32  [2][1088]       : 8704
#define SM_BYTES 150528

__device__ float    g_xz[(size_t)BATCH * TSTEPS * FOURU];
__device__ uint4    g_Afrag[(size_t)NMTILE * NKSTEP * 2 * 32];
__device__ uint4    g_Wfrag[(size_t)NKSTEP * 2 * 64 * 32 * 2];
__device__ float    g_h[2][BATCH][UNITS];          // fp32 (for fc tail)
__device__ uint32_t g_hfH[2][NBG][32 * 128];       // A-fragment hi words
__device__ uint32_t g_hfL[2][NBG][32 * 128];       // A-fragment lo words
__device__ unsigned g_sub[NBG][8][8];              // two-level barrier subs
__device__ unsigned g_master[NBG][32];
__device__ unsigned g_gen[NBG * 32];

__device__ __forceinline__ float fsig(float x) {
    return __fdividef(1.f, 1.f + __expf(-x));
}
__device__ __forceinline__ float ftanh(float x) {
    return 1.f - __fdividef(2.f, __expf(2.f * x) + 1.f);
}
__device__ __forceinline__ unsigned atom_add_acqrel(unsigned* p, unsigned v) {
    unsigned old;
    asm volatile("atom.acq_rel.gpu.global.add.u32 %0, [%1], %2;"
                 : "=r"(old) : "l"(p), "r"(v) : "memory");
    return old;
}
__device__ __forceinline__ void st_release(unsigned* p, unsigned v) {
    asm volatile("st.release.gpu.global.u32 [%0], %1;" :: "l"(p), "r"(v) : "memory");
}
__device__ __forceinline__ unsigned ld_acquire(const unsigned* p) {
    unsigned v;
    asm volatile("ld.acquire.gpu.global.u32 %0, [%1];" : "=r"(v) : "l"(p) : "memory");
    return v;
}
__device__ __forceinline__ uint32_t pack_split_hi(float a, float b) {
    __nv_bfloat16 ha = __float2bfloat16(a), hb = __float2bfloat16(b);
    return (uint32_t)*(uint16_t*)&ha | ((uint32_t)*(uint16_t*)&hb << 16);
}
__device__ __forceinline__ uint32_t pack_split_lo(float a, float b) {
    __nv_bfloat16 ha = __float2bfloat16(a), hb = __float2bfloat16(b);
    __nv_bfloat16 la = __float2bfloat16(a - __bfloat162float(ha));
    __nv_bfloat16 lb = __float2bfloat16(b - __bfloat162float(hb));
    return (uint32_t)*(uint16_t*)&la | ((uint32_t)*(uint16_t*)&lb << 16);
}
__device__ __forceinline__ uint32_t smem_u32(const void* p) {
    return (uint32_t)__cvta_generic_to_shared(p);
}

__global__ void init_kernel() {
    int i = blockIdx.x * blockDim.x + threadIdx.x;
    if (i < 2 * BATCH * UNITS) ((float*)g_h)[i] = 0.f;
    if (i < 2 * NBG * 32 * 128) {
        ((uint32_t*)g_hfH)[i] = 0u;
        ((uint32_t*)g_hfL)[i] = 0u;
    }
    if (i < NBG * 8 * 8) ((unsigned*)g_sub)[i] = 0u;
    if (i < NBG * 32) { ((unsigned*)g_master)[i] = 0u; g_gen[i] = 0u; }
}

// ---- prep A (unchanged) ----------------------------------------------------
__global__ __launch_bounds__(256) void prep_A(const float* __restrict__ A) {
    int f = blockIdx.x * 256 + threadIdx.x;
    int t = f & 31, ks = (f >> 5) & 31, mt = f >> 10;
    uint32_t hi[4], lo[4];
#pragma unroll
    for (int r = 0; r < 4; r++) {
        int m  = mt * 16 + (r & 1) * 8 + (t >> 2);
        int k0 = ks * 16 + ((r & 2) << 2) + ((t & 3) << 1);
        float2 av = *(const float2*)(A + (size_t)m * DIN + k0);
        hi[r] = pack_split_hi(av.x, av.y);
        lo[r] = pack_split_lo(av.x, av.y);
    }
    size_t ib = ((size_t)mt * 32 + ks) * 2;
    g_Afrag[ib * 32 + t]       = make_uint4(hi[0], hi[1], hi[2], hi[3]);
    g_Afrag[(ib + 1) * 32 + t] = make_uint4(lo[0], lo[1], lo[2], lo[3]);
}

// ---- prep W (unchanged) ----------------------------------------------------
__global__ __launch_bounds__(256) void prep_W(const float* __restrict__ W) {
    int f = blockIdx.x * 256 + threadIdx.x;
    int t = f & 31, ngrp = (f >> 5) & 63, ks = f >> 11;
    uint32_t hi[8], lo[8];
#pragma unroll
    for (int nblk = 0; nblk < 4; nblk++)
#pragma unroll
        for (int reg = 0; reg < 2; reg++) {
            int k0 = ks * 16 + reg * 8 + (t & 3) * 2;
            int n  = ngrp * 32 + nblk * 8 + (t >> 2);
            float w0 = W[(size_t)k0 * FOURU + n];
            float w1 = W[(size_t)(k0 + 1) * FOURU + n];
            hi[nblk * 2 + reg] = pack_split_hi(w0, w1);
            lo[nblk * 2 + reg] = pack_split_lo(w0, w1);
        }
    size_t wb = (((size_t)ks * 2 + 0) * 64 + ngrp) * 32 + t;
    size_t wl = (((size_t)ks * 2 + 1) * 64 + ngrp) * 32 + t;
    g_Wfrag[wb * 2]     = make_uint4(hi[0], hi[1], hi[2], hi[3]);
    g_Wfrag[wb * 2 + 1] = make_uint4(hi[4], hi[5], hi[6], hi[7]);
    g_Wfrag[wl * 2]     = make_uint4(lo[0], lo[1], lo[2], lo[3]);
    g_Wfrag[wl * 2 + 1] = make_uint4(lo[4], lo[5], lo[6], lo[7]);
}

#define MMA16816(c, a, b0v, b1v)                                              \
    asm volatile(                                                             \
        "mma.sync.aligned.m16n8k16.row.col.f32.bf16.bf16.f32 "                \
        "{%0,%1,%2,%3}, {%4,%5,%6,%7}, {%8,%9}, {%0,%1,%2,%3};"               \
        : "+f"((c)[0]), "+f"((c)[1]), "+f"((c)[2]), "+f"((c)[3])              \
        : "r"((a).x), "r"((a).y), "r"((a).z), "r"((a).w),                     \
          "r"(b0v), "r"(b1v))

#define LDSM4(r, addr)                                                        \
    asm volatile("ldmatrix.sync.aligned.m8n8.x4.shared.b16 "                  \
                 "{%0,%1,%2,%3}, [%4];"                                       \
                 : "=r"((r).x), "=r"((r).y), "=r"((r).z), "=r"((r).w)         \
                 : "r"(addr))

// ---- xz GEMM (unchanged) ---------------------------------------------------
__global__ __launch_bounds__(256) void gemm_mma(const float* __restrict__ bias) {
    const int tid = threadIdx.x;
    const int t = tid & 31, wid = tid >> 5;
    const int wm = wid & 1, wn = wid >> 1;
    const int mtb = blockIdx.y * 8 + wm * 4;
    const int ngrp = blockIdx.x * 4 + wn;

    float acc[4][4][4];
#pragma unroll
    for (int mi = 0; mi < 4; mi++)
#pragma unroll
        for (int ni = 0; ni < 4; ni++)
#pragma unroll
            for (int c = 0; c < 4; c++) acc[mi][ni][c] = 0.f;

#pragma unroll 2
    for (int ks = 0; ks < NKSTEP; ks++) {
        uint4 ah[4], al[4];
#pragma unroll
        for (int mi = 0; mi < 4; mi++) {
            size_t ib = ((size_t)(mtb + mi) * 32 + ks) * 2;
            ah[mi] = g_Afrag[ib * 32 + t];
            al[mi] = g_Afrag[(ib + 1) * 32 + t];
        }
        size_t wb = (((size_t)ks * 2 + 0) * 64 + ngrp) * 32 + t;
        size_t wl = (((size_t)ks * 2 + 1) * 64 + ngrp) * 32 + t;
        uint4 bh0 = g_Wfrag[wb * 2], bh1 = g_Wfrag[wb * 2 + 1];
        uint4 bl0 = g_Wfrag[wl * 2], bl1 = g_Wfrag[wl * 2 + 1];
        uint32_t bh[8] = {bh0.x, bh0.y, bh0.z, bh0.w, bh1.x, bh1.y, bh1.z, bh1.w};
        uint32_t bl[8] = {bl0.x, bl0.y, bl0.z, bl0.w, bl1.x, bl1.y, bl1.z, bl1.w};

#pragma unroll
        for (int mi = 0; mi < 4; mi++)
#pragma unroll
            for (int ni = 0; ni < 4; ni++) {
                MMA16816(acc[mi][ni], ah[mi], bh[ni * 2], bh[ni * 2 + 1]);
                MMA16816(acc[mi][ni], ah[mi], bl[ni * 2], bl[ni * 2 + 1]);
                MMA16816(acc[mi][ni], al[mi], bh[ni * 2], bh[ni * 2 + 1]);
            }
    }

    const int colbase = blockIdx.x * 128 + wn * 32 + (t & 3) * 2;
    const int rowbase = blockIdx.y * 128 + wm * 64 + (t >> 2);
    float2 bv[4];
#pragma unroll
    for (int ni = 0; ni < 4; ni++)
        bv[ni] = *(const float2*)(bias + colbase + ni * 8);
#pragma unroll
    for (int mi = 0; mi < 4; mi++) {
        int r0 = rowbase + mi * 16;
#pragma unroll
        for (int ni = 0; ni < 4; ni++) {
            int col = colbase + ni * 8;
            float2 o0 = make_float2(acc[mi][ni][0] + bv[ni].x,
                                    acc[mi][ni][1] + bv[ni].y);
            float2 o1 = make_float2(acc[mi][ni][2] + bv[ni].x,
                                    acc[mi][ni][3] + bv[ni].y);
            __stcs((float2*)(g_xz + (size_t)r0 * FOURU + col), o0);
            __stcs((float2*)(g_xz + (size_t)(r0 + 8) * FOURU + col), o1);
        }
    }
}

// ---- persistent LSTM recurrence --------------------------------------------
// Producers publish h as split-bf16 MMA A-fragments (CTA (ug,bg) fills k-tile
// kt=ug of group bg). Consumers mma directly from __ldcg fragment loads — no
// A staging, no A LDSM, no cvt chain. Two-level barrier arrival.
__global__ __launch_bounds__(TPB, 1) void lstm_recur(const float* __restrict__ R)
{
    extern __shared__ char smc[];
    __nv_bfloat16* Bhi = (__nv_bfloat16*)(smc + SM_BHI);
    __nv_bfloat16* Blo = (__nv_bfloat16*)(smc + SM_BLO);
    float* zbuf = (float*)(smc + SM_Z);       // [2][16][68]
    float* xzs  = (float*)(smc + SM_XZ);

    const int tid = threadIdx.x;
    const int wid = tid >> 5, lane = tid & 31;
    const int ug = blockIdx.x >> 2, bg = blockIdx.x & 3;
    const int u0 = ug * 16, b0 = bg * 16;

    // ---- build B (R slice) once: B[n][k] = R[k][g*512+u0+j], n = g*16+j ----
    for (int i = tid; i < 64 * 512; i += TPB) {
        int k = i & 511, n = i >> 9;
        int g = n >> 4, j = n & 15;
        float v = R[(size_t)k * FOURU + g * UNITS + u0 + j];
        __nv_bfloat16 hb = __float2bfloat16(v);
        __nv_bfloat16 lb = __float2bfloat16(v - __bfloat162float(hb));
        Bhi[n * 520 + k] = hb;
        Blo[n * 520 + k] = lb;
    }

    // ---- xz staging map: thread -> (pb, pg, pq) ----------------------------
    const int pb = tid >> 4, pg = (tid >> 2) & 3, pq = tid & 3;
    const float* xz_thread = g_xz + (size_t)(b0 + pb) * TSTEPS * FOURU
                             + pg * UNITS + u0 + pq * 4;
    {
        float4 v = __ldcs((const float4*)xz_thread);
        float vv[4] = {v.x, v.y, v.z, v.w};
#pragma unroll
        for (int j = 0; j < 4; j++)
            xzs[pg * 272 + (pq * 4 + j) * 17 + pb] = vv[j];
    }
    __syncthreads();

    // ---- warp roles + B addresses ------------------------------------------
    const int khalf = wid >> 2, npair = wid & 3;
    const int bRow = npair * 16 + ((lane >> 4) & 1) * 8 + (lane & 7);
    const int bKof = ((lane >> 3) & 1) * 16;
    const uint32_t bHiAddr = smem_u32(smc + SM_BHI) + bRow * 1040 + bKof;
    const uint32_t bLoAddr = smem_u32(smc + SM_BLO) + bRow * 1040 + bKof;

    // preload this warp's B-hi fragments (time-invariant)
    uint4 Bh[16];
#pragma unroll
    for (int i = 0; i < 16; i++)
        LDSM4(Bh[i], bHiAddr + (khalf * 16 + i) * 32);

    // gates map: b = tid>>4, u(local) = tid&15
    const int b_l = tid >> 4, j_l = tid & 15;
    // producer fragment word index for this thread-pair
    const int kl = j_l & 14;
    const int lane_t = (b_l & 7) * 4 + ((kl >> 1) & 3);
    const int frag_r = (b_l >> 3) | (((kl >> 3) & 1) << 1);
    const int frag_idx = ug * 128 + lane_t * 4 + frag_r;

    unsigned* subp   = &g_sub[bg][ug & 7][0];
    unsigned* master = &g_master[bg][0];
    unsigned* gen    = &g_gen[bg * 32];

    float c_state = 0.f;

    for (int t = 0; t < TSTEPS; t++) {
        const int par = t & 1;
        float4 xnext = make_float4(0.f, 0.f, 0.f, 0.f);
        if (t + 1 < TSTEPS)
            xnext = __ldcs((const float4*)(xz_thread + (size_t)(t + 1) * FOURU));

        // ---- MMA directly from fragment GMEM (A) + SMEM (B-lo) + regs (B-hi)
        const uint4* AH = (const uint4*)&g_hfH[par][bg][0];
        const uint4* AL = (const uint4*)&g_hfL[par][bg][0];
        float acc0[4] = {0.f, 0.f, 0.f, 0.f};
        float acc1[4] = {0.f, 0.f, 0.f, 0.f};
#pragma unroll
        for (int i = 0; i < 16; i++) {
            int kt = khalf * 16 + i;
            uint4 ah = __ldcg(&AH[kt * 32 + lane]);
            uint4 al = __ldcg(&AL[kt * 32 + lane]);
            uint4 bl;
            LDSM4(bl, bLoAddr + kt * 32);
            MMA16816(acc0, ah, Bh[i].x, Bh[i].y);
            MMA16816(acc1, ah, Bh[i].z, Bh[i].w);
            MMA16816(acc0, ah, bl.x, bl.y);
            MMA16816(acc1, ah, bl.z, bl.w);
            MMA16816(acc0, al, Bh[i].x, Bh[i].y);
            MMA16816(acc1, al, Bh[i].z, Bh[i].w);
        }

        // ---- both k-halves write partial z to their own buffer ----
        {
            float* zb = zbuf + khalf * 1088;
            int ra = lane >> 2, cb = (lane & 3) * 2;
            int n0 = npair * 16 + cb, n1 = npair * 16 + 8 + cb;
            *(float2*)&zb[ra * 68 + n0]       = make_float2(acc0[0], acc0[1]);
            *(float2*)&zb[(ra + 8) * 68 + n0] = make_float2(acc0[2], acc0[3]);
            *(float2*)&zb[ra * 68 + n1]       = make_float2(acc1[0], acc1[1]);
            *(float2*)&zb[(ra + 8) * 68 + n1] = make_float2(acc1[2], acc1[3]);
        }
        __syncthreads();

        // ---- gates + fragment publish ----
        {
            const float* z0 = zbuf + b_l * 68 + j_l;
            const float* z1 = zbuf + 1088 + b_l * 68 + j_l;
            const float* xb = xzs + par * 1088 + j_l * 17 + b_l;
            float zv1 = z0[0]  + z1[0]  + xb[0];
            float zv2 = z0[16] + z1[16] + xb[272];
            float zv3 = z0[32] + z1[32] + xb[544];
            float zv4 = z0[48] + z1[48] + xb[816];
            float v1 = ftanh(zv1);
            float v2 = fsig(zv2);
            float v3 = fsig(zv3);
            float v4 = fsig(zv4);
            c_state = v1 * v2 + v3 * c_state;
            float hnew = v4 * ftanh(c_state);
            __stcg(&g_h[par ^ 1][b0 + b_l][u0 + j_l], hnew);

            float hpart = __shfl_xor_sync(0xffffffffu, hnew, 1);
            float lowv  = (j_l & 1) ? hpart : hnew;
            float highv = (j_l & 1) ? hnew  : hpart;
            uint32_t hw;
            asm("cvt.rn.bf16x2.f32 %0, %1, %2;" : "=r"(hw) : "f"(highv), "f"(lowv));
            if ((j_l & 1) == 0) {
                __stcg(&g_hfH[par ^ 1][bg][frag_idx], hw);
            } else {
                float fh = __uint_as_float(hw & 0xffff0000u);
                float fl = __uint_as_float(hw << 16);
                uint32_t lw;
                asm("cvt.rn.bf16x2.f32 %0, %1, %2;"
                    : "=r"(lw) : "f"(highv - fh), "f"(lowv - fl));
                __stcg(&g_hfL[par ^ 1][bg][frag_idx], lw);
            }
        }

        // ---- barrier: two-level arrive early, stage xz, poll ----
        __syncthreads();
        if (tid == 0) {
            unsigned ps = atom_add_acqrel(subp, 1u);
            if ((ps & 3u) == 3u) {
                unsigned pm = atom_add_acqrel(master, 1u);
                if ((pm & 7u) == 7u)
                    st_release(gen, (unsigned)(t + 1));
            }
        }
        if (t + 1 < TSTEPS) {
            float vv[4] = {xnext.x, xnext.y, xnext.z, xnext.w};
            float* dst = xzs + ((t + 1) & 1) * 1088;
#pragma unroll
            for (int j = 0; j < 4; j++)
                dst[pg * 272 + (pq * 4 + j) * 17 + pb] = vv[j];
        }
        if (tid == 0) {
            while (ld_acquire(gen) < (unsigned)(t + 1)) { }
        }
        __syncthreads();
    }
}

// ---- final dense + softmax --------------------------------------------------
__global__ void fc_softmax(const float* __restrict__ fc_w,
                           const float* __restrict__ fc_b,
                           float* __restrict__ out)
{
    const int b = blockIdx.x;
    const int l = threadIdx.x;
    float a0 = 0.f, a1 = 0.f, a2 = 0.f, a3 = 0.f;
    const float* hg = &g_h[0][b][0];   // t=1023 wrote parity 0
    for (int k = l * 16; k < l * 16 + 16; k += 4) {
        float4 hv = *(const float4*)(hg + k);
        float hx[4] = {hv.x, hv.y, hv.z, hv.w};
#pragma unroll
        for (int q = 0; q < 4; q++) {
            float4 wv = *(const float4*)&fc_w[(k + q) * 4];
            a0 += hx[q] * wv.x; a1 += hx[q] * wv.y;
            a2 += hx[q] * wv.z; a3 += hx[q] * wv.w;
        }
    }
#pragma unroll
    for (int o = 16; o > 0; o >>= 1) {
        a0 += __shfl_down_sync(0xffffffffu, a0, o);
        a1 += __shfl_down_sync(0xffffffffu, a1, o);
        a2 += __shfl_down_sync(0xffffffffu, a2, o);
        a3 += __shfl_down_sync(0xffffffffu, a3, o);
    }
    if (l == 0) {
        float z0 = a0 + fc_b[0], z1 = a1 + fc_b[1];
        float z2 = a2 + fc_b[2], z3 = a3 + fc_b[3];
        float m = fmaxf(fmaxf(z0, z1), fmaxf(z2, z3));
        float e0 = __expf(z0 - m), e1 = __expf(z1 - m);
        float e2 = __expf(z2 - m), e3 = __expf(z3 - m);
        float inv = __fdividef(1.f, e0 + e1 + e2 + e3);
        out[b * 4 + 0] = e0 * inv;
        out[b * 4 + 1] = e1 * inv;
        out[b * 4 + 2] = e2 * inv;
        out[b * 4 + 3] = e3 * inv;
    }
}

// ---------------------------------------------------------------------------
extern "C" void kernel_launch(void* const* d_in, const int* in_sizes, int n_in,
                              void* d_out, int out_size)
{
    const float* tx      = (const float*)d_in[0];
    const float* kernelW = (const float*)d_in[1];
    const float* R       = (const float*)d_in[2];
    const float* bias    = (const float*)d_in[3];
    const float* fc_w    = (const float*)d_in[4];
    const float* fc_b    = (const float*)d_in[5];
    float* out           = (float*)d_out;

    cudaFuncSetAttribute(lstm_recur,
                         cudaFuncAttributeMaxDynamicSharedMemorySize, SM_BYTES);

    init_kernel<<<(2 * BATCH * UNITS + 255) / 256, 256>>>();
    prep_A<<<16384, 256>>>(tx);
    prep_W<<<256, 256>>>(kernelW);
    gemm_mma<<<dim3(16, 512), 256>>>(bias);
    lstm_recur<<<NCTA, TPB, SM_BYTES>>>(R);
    fc_softmax<<<BATCH, 32>>>(fc_w, fc_b, out);
    (void)in_sizes; (void)n_in; (void)out_size;
}

// round 14
// speedup vs baseline: 1.0661x; 1.0661x over previous
#include <cuda_runtime.h>
#include <cuda_bf16.h>
#include <cstdint>

// LSTM  B=64, T=1024, D=512, U=512, OUT=4
#define BATCH    64
#define TSTEPS   1024
#define DIN      512
#define UNITS    512
#define FOURU    2048
#define NCTA     128
#define TPB      256
#define NBG      4
#define GROUP_CTAS 32
#define NMTILE   4096
#define NKSTEP   32

// recurrence smem offsets (bytes)
#define SM_BHI   0            // bf16 [64 n][520]     : 66560
#define SM_BLO   66560        // bf16 [64 n][520]     : 66560
#define SM_AHI   133120       // bf16 [16 b][520]     : 16640
#define SM_ALO   149760       // bf16 [16 b][520]     : 16640
#define SM_Z     166400       // f32  [2][16 b][68]   : 8704
#define SM_XZ    175104       // f32  [2][1088]       : 8704
#define SM_BYTES 183808

__device__ float    g_xz[(size_t)BATCH * TSTEPS * FOURU];
__device__ uint4    g_Afrag[(size_t)NMTILE * NKSTEP * 2 * 32];
__device__ uint4    g_Wfrag[(size_t)NKSTEP * 2 * 64 * 32 * 2];
__device__ float    g_h[2][BATCH][UNITS];        // batch-major
__device__ unsigned g_sub[NBG][8][8];            // two-level barrier: 8 subs x 4 CTAs
__device__ unsigned g_master[NBG][32];
__device__ unsigned g_gen[NBG * 32];

__device__ __forceinline__ float fsig(float x) {
    return __fdividef(1.f, 1.f + __expf(-x));
}
__device__ __forceinline__ float ftanh(float x) {
    return 1.f - __fdividef(2.f, __expf(2.f * x) + 1.f);
}
__device__ __forceinline__ unsigned atom_add_acqrel(unsigned* p, unsigned v) {
    unsigned old;
    asm volatile("atom.acq_rel.gpu.global.add.u32 %0, [%1], %2;"
                 : "=r"(old) : "l"(p), "r"(v) : "memory");
    return old;
}
__device__ __forceinline__ void st_release(unsigned* p, unsigned v) {
    asm volatile("st.release.gpu.global.u32 [%0], %1;" :: "l"(p), "r"(v) : "memory");
}
__device__ __forceinline__ unsigned ld_acquire(const unsigned* p) {
    unsigned v;
    asm volatile("ld.acquire.gpu.global.u32 %0, [%1];" : "=r"(v) : "l"(p) : "memory");
    return v;
}
__device__ __forceinline__ uint32_t pack_split_hi(float a, float b) {
    __nv_bfloat16 ha = __float2bfloat16(a), hb = __float2bfloat16(b);
    return (uint32_t)*(uint16_t*)&ha | ((uint32_t)*(uint16_t*)&hb << 16);
}
__device__ __forceinline__ uint32_t pack_split_lo(float a, float b) {
    __nv_bfloat16 ha = __float2bfloat16(a), hb = __float2bfloat16(b);
    __nv_bfloat16 la = __float2bfloat16(a - __bfloat162float(ha));
    __nv_bfloat16 lb = __float2bfloat16(b - __bfloat162float(hb));
    return (uint32_t)*(uint16_t*)&la | ((uint32_t)*(uint16_t*)&lb << 16);
}
__device__ __forceinline__ uint32_t smem_u32(const void* p) {
    return (uint32_t)__cvta_generic_to_shared(p);
}

__global__ void init_kernel() {
    int i = blockIdx.x * blockDim.x + threadIdx.x;
    if (i < 2 * BATCH * UNITS) ((float*)g_h)[i] = 0.f;
    if (i < NBG * 8 * 8) ((unsigned*)g_sub)[i] = 0u;
    if (i < NBG * 32) { ((unsigned*)g_master)[i] = 0u; g_gen[i] = 0u; }
}

// ---- prep A (unchanged) ----------------------------------------------------
__global__ __launch_bounds__(256) void prep_A(const float* __restrict__ A) {
    int f = blockIdx.x * 256 + threadIdx.x;
    int t = f & 31, ks = (f >> 5) & 31, mt = f >> 10;
    uint32_t hi[4], lo[4];
#pragma unroll
    for (int r = 0; r < 4; r++) {
        int m  = mt * 16 + (r & 1) * 8 + (t >> 2);
        int k0 = ks * 16 + ((r & 2) << 2) + ((t & 3) << 1);
        float2 av = *(const float2*)(A + (size_t)m * DIN + k0);
        hi[r] = pack_split_hi(av.x, av.y);
        lo[r] = pack_split_lo(av.x, av.y);
    }
    size_t ib = ((size_t)mt * 32 + ks) * 2;
    g_Afrag[ib * 32 + t]       = make_uint4(hi[0], hi[1], hi[2], hi[3]);
    g_Afrag[(ib + 1) * 32 + t] = make_uint4(lo[0], lo[1], lo[2], lo[3]);
}

// ---- prep W (unchanged) ----------------------------------------------------
__global__ __launch_bounds__(256) void prep_W(const float* __restrict__ W) {
    int f = blockIdx.x * 256 + threadIdx.x;
    int t = f & 31, ngrp = (f >> 5) & 63, ks = f >> 11;
    uint32_t hi[8], lo[8];
#pragma unroll
    for (int nblk = 0; nblk < 4; nblk++)
#pragma unroll
        for (int reg = 0; reg < 2; reg++) {
            int k0 = ks * 16 + reg * 8 + (t & 3) * 2;
            int n  = ngrp * 32 + nblk * 8 + (t >> 2);
            float w0 = W[(size_t)k0 * FOURU + n];
            float w1 = W[(size_t)(k0 + 1) * FOURU + n];
            hi[nblk * 2 + reg] = pack_split_hi(w0, w1);
            lo[nblk * 2 + reg] = pack_split_lo(w0, w1);
        }
    size_t wb = (((size_t)ks * 2 + 0) * 64 + ngrp) * 32 + t;
    size_t wl = (((size_t)ks * 2 + 1) * 64 + ngrp) * 32 + t;
    g_Wfrag[wb * 2]     = make_uint4(hi[0], hi[1], hi[2], hi[3]);
    g_Wfrag[wb * 2 + 1] = make_uint4(hi[4], hi[5], hi[6], hi[7]);
    g_Wfrag[wl * 2]     = make_uint4(lo[0], lo[1], lo[2], lo[3]);
    g_Wfrag[wl * 2 + 1] = make_uint4(lo[4], lo[5], lo[6], lo[7]);
}

#define MMA16816(c, a, b0v, b1v)                                              \
    asm volatile(                                                             \
        "mma.sync.aligned.m16n8k16.row.col.f32.bf16.bf16.f32 "                \
        "{%0,%1,%2,%3}, {%4,%5,%6,%7}, {%8,%9}, {%0,%1,%2,%3};"               \
        : "+f"((c)[0]), "+f"((c)[1]), "+f"((c)[2]), "+f"((c)[3])              \
        : "r"((a).x), "r"((a).y), "r"((a).z), "r"((a).w),                     \
          "r"(b0v), "r"(b1v))

#define LDSM4(r, addr)                                                        \
    asm volatile("ldmatrix.sync.aligned.m8n8.x4.shared.b16 "                  \
                 "{%0,%1,%2,%3}, [%4];"                                       \
                 : "=r"((r).x), "=r"((r).y), "=r"((r).z), "=r"((r).w)         \
                 : "r"(addr))

// ---- xz GEMM (unchanged) ---------------------------------------------------
__global__ __launch_bounds__(256) void gemm_mma(const float* __restrict__ bias) {
    const int tid = threadIdx.x;
    const int t = tid & 31, wid = tid >> 5;
    const int wm = wid & 1, wn = wid >> 1;
    const int mtb = blockIdx.y * 8 + wm * 4;
    const int ngrp = blockIdx.x * 4 + wn;

    float acc[4][4][4];
#pragma unroll
    for (int mi = 0; mi < 4; mi++)
#pragma unroll
        for (int ni = 0; ni < 4; ni++)
#pragma unroll
            for (int c = 0; c < 4; c++) acc[mi][ni][c] = 0.f;

#pragma unroll 2
    for (int ks = 0; ks < NKSTEP; ks++) {
        uint4 ah[4], al[4];
#pragma unroll
        for (int mi = 0; mi < 4; mi++) {
            size_t ib = ((size_t)(mtb + mi) * 32 + ks) * 2;
            ah[mi] = g_Afrag[ib * 32 + t];
            al[mi] = g_Afrag[(ib + 1) * 32 + t];
        }
        size_t wb = (((size_t)ks * 2 + 0) * 64 + ngrp) * 32 + t;
        size_t wl = (((size_t)ks * 2 + 1) * 64 + ngrp) * 32 + t;
        uint4 bh0 = g_Wfrag[wb * 2], bh1 = g_Wfrag[wb * 2 + 1];
        uint4 bl0 = g_Wfrag[wl * 2], bl1 = g_Wfrag[wl * 2 + 1];
        uint32_t bh[8] = {bh0.x, bh0.y, bh0.z, bh0.w, bh1.x, bh1.y, bh1.z, bh1.w};
        uint32_t bl[8] = {bl0.x, bl0.y, bl0.z, bl0.w, bl1.x, bl1.y, bl1.z, bl1.w};

#pragma unroll
        for (int mi = 0; mi < 4; mi++)
#pragma unroll
            for (int ni = 0; ni < 4; ni++) {
                MMA16816(acc[mi][ni], ah[mi], bh[ni * 2], bh[ni * 2 + 1]);
                MMA16816(acc[mi][ni], ah[mi], bl[ni * 2], bl[ni * 2 + 1]);
                MMA16816(acc[mi][ni], al[mi], bh[ni * 2], bh[ni * 2 + 1]);
            }
    }

    const int colbase = blockIdx.x * 128 + wn * 32 + (t & 3) * 2;
    const int rowbase = blockIdx.y * 128 + wm * 64 + (t >> 2);
    float2 bv[4];
#pragma unroll
    for (int ni = 0; ni < 4; ni++)
        bv[ni] = *(const float2*)(bias + colbase + ni * 8);
#pragma unroll
    for (int mi = 0; mi < 4; mi++) {
        int r0 = rowbase + mi * 16;
#pragma unroll
        for (int ni = 0; ni < 4; ni++) {
            int col = colbase + ni * 8;
            float2 o0 = make_float2(acc[mi][ni][0] + bv[ni].x,
                                    acc[mi][ni][1] + bv[ni].y);
            float2 o1 = make_float2(acc[mi][ni][2] + bv[ni].x,
                                    acc[mi][ni][3] + bv[ni].y);
            __stcs((float2*)(g_xz + (size_t)r0 * FOURU + col), o0);
            __stcs((float2*)(g_xz + (size_t)(r0 + 8) * FOURU + col), o1);
        }
    }
}

// ---- persistent LSTM recurrence (R12 data path + two-level barrier) --------
__global__ __launch_bounds__(TPB, 1) void lstm_recur(const float* __restrict__ R)
{
    extern __shared__ char smc[];
    __nv_bfloat16* Bhi = (__nv_bfloat16*)(smc + SM_BHI);
    __nv_bfloat16* Blo = (__nv_bfloat16*)(smc + SM_BLO);
    uint32_t* AhiW = (uint32_t*)(smc + SM_AHI);
    uint32_t* AloW = (uint32_t*)(smc + SM_ALO);
    float* zbuf = (float*)(smc + SM_Z);       // [2][16][68]
    float* xzs  = (float*)(smc + SM_XZ);

    const int tid = threadIdx.x;
    const int wid = tid >> 5, lane = tid & 31;
    const int ug = blockIdx.x >> 2, bg = blockIdx.x & 3;
    const int u0 = ug * 16, b0 = bg * 16;

    // ---- build B (R slice) once: B[n][k] = R[k][g*512+u0+j], n = g*16+j ----
    for (int i = tid; i < 64 * 512; i += TPB) {
        int k = i & 511, n = i >> 9;
        int g = n >> 4, j = n & 15;
        float v = R[(size_t)k * FOURU + g * UNITS + u0 + j];
        __nv_bfloat16 hb = __float2bfloat16(v);
        __nv_bfloat16 lb = __float2bfloat16(v - __bfloat162float(hb));
        Bhi[n * 520 + k] = hb;
        Blo[n * 520 + k] = lb;
    }

    // ---- xz staging map: thread -> (pb, pg, pq) ----------------------------
    const int pb = tid >> 4, pg = (tid >> 2) & 3, pq = tid & 3;
    const float* xz_thread = g_xz + (size_t)(b0 + pb) * TSTEPS * FOURU
                             + pg * UNITS + u0 + pq * 4;
    {
        float4 v = __ldcs((const float4*)xz_thread);
        float vv[4] = {v.x, v.y, v.z, v.w};
#pragma unroll
        for (int j = 0; j < 4; j++)
            xzs[pg * 272 + (pq * 4 + j) * 17 + pb] = vv[j];
    }
    __syncthreads();

    // ---- lane-invariant LDSM addresses -------------------------------------
    const int khalf = wid >> 2, npair = wid & 3;
    const int aRow = (lane & 7) + ((lane >> 3) & 1) * 8;
    const int aKof = ((lane >> 4) & 1) * 16;            // bytes
    const uint32_t aHiAddr = smem_u32(smc + SM_AHI) + aRow * 1040 + aKof;
    const uint32_t aLoAddr = smem_u32(smc + SM_ALO) + aRow * 1040 + aKof;
    const int bRow = npair * 16 + ((lane >> 4) & 1) * 8 + (lane & 7);
    const int bKof = ((lane >> 3) & 1) * 16;
    const uint32_t bHiAddr = smem_u32(smc + SM_BHI) + bRow * 1040 + bKof;
    const uint32_t bLoAddr = smem_u32(smc + SM_BLO) + bRow * 1040 + bKof;

    // ---- preload this warp's B-hi fragments into registers (time-invariant)
    uint4 Bh[16];
#pragma unroll
    for (int i = 0; i < 16; i++)
        LDSM4(Bh[i], bHiAddr + (khalf * 16 + i) * 32);

    // A-staging map: b = tid>>4, 8 chunks of 4 floats at u = (tid&15)*4+q*64
    const int sb = tid >> 4, su = (tid & 15) * 4;
    // gates map (coalesced h writeback): b = tid>>4, u = tid&15
    const int b_l = tid >> 4, j_l = tid & 15;

    unsigned* subp   = &g_sub[bg][ug & 7][0];
    unsigned* master = &g_master[bg][0];
    unsigned* gen    = &g_gen[bg * 32];

    float c_state = 0.f;

    for (int t = 0; t < TSTEPS; t++) {
        const int par = t & 1;
        float4 xnext = make_float4(0.f, 0.f, 0.f, 0.f);
        if (t + 1 < TSTEPS)
            xnext = __ldcs((const float4*)(xz_thread + (size_t)(t + 1) * FOURU));

        // ---- stage A = h(t)[16 b][512 k] as split bf16 ----
        const float* hsrc = &g_h[par][b0 + sb][0];
#pragma unroll
        for (int q = 0; q < 8; q++) {
            int u = su + q * 64;
            float4 v = __ldcg((const float4*)(hsrc + u));
            uint32_t h01, h23, l01, l23;
            asm("cvt.rn.bf16x2.f32 %0, %1, %2;" : "=r"(h01) : "f"(v.y), "f"(v.x));
            asm("cvt.rn.bf16x2.f32 %0, %1, %2;" : "=r"(h23) : "f"(v.w), "f"(v.z));
            float f0 = __uint_as_float(h01 << 16);
            float f1 = __uint_as_float(h01 & 0xffff0000u);
            float f2 = __uint_as_float(h23 << 16);
            float f3 = __uint_as_float(h23 & 0xffff0000u);
            asm("cvt.rn.bf16x2.f32 %0, %1, %2;"
                : "=r"(l01) : "f"(v.y - f1), "f"(v.x - f0));
            asm("cvt.rn.bf16x2.f32 %0, %1, %2;"
                : "=r"(l23) : "f"(v.w - f3), "f"(v.z - f2));
            int w = sb * 260 + u / 2;
            AhiW[w] = h01; AhiW[w + 1] = h23;
            AloW[w] = l01; AloW[w + 1] = l23;
        }
        __syncthreads();

        // ---- MMA: n-tiles {2*npair, 2*npair+1}, k-half khalf ----
        float acc0[4] = {0.f, 0.f, 0.f, 0.f};
        float acc1[4] = {0.f, 0.f, 0.f, 0.f};
#pragma unroll
        for (int i = 0; i < 16; i++) {
            uint32_t ofs = (khalf * 16 + i) * 32;
            uint4 ah, al, bl;
            LDSM4(ah, aHiAddr + ofs);
            LDSM4(al, aLoAddr + ofs);
            LDSM4(bl, bLoAddr + ofs);
            MMA16816(acc0, ah, Bh[i].x, Bh[i].y);
            MMA16816(acc1, ah, Bh[i].z, Bh[i].w);
            MMA16816(acc0, ah, bl.x, bl.y);
            MMA16816(acc1, ah, bl.z, bl.w);
            MMA16816(acc0, al, Bh[i].x, Bh[i].y);
            MMA16816(acc1, al, Bh[i].z, Bh[i].w);
        }

        // ---- both halves write partial z to their own buffer ----
        {
            float* zb = zbuf + khalf * 1088;
            int ra = lane >> 2, cb = (lane & 3) * 2;
            int n0 = npair * 16 + cb, n1 = npair * 16 + 8 + cb;
            *(float2*)&zb[ra * 68 + n0]       = make_float2(acc0[0], acc0[1]);
            *(float2*)&zb[(ra + 8) * 68 + n0] = make_float2(acc0[2], acc0[3]);
            *(float2*)&zb[ra * 68 + n1]       = make_float2(acc1[0], acc1[1]);
            *(float2*)&zb[(ra + 8) * 68 + n1] = make_float2(acc1[2], acc1[3]);
        }
        __syncthreads();

        // ---- gates: thread (b_l = tid>>4, j_l = tid&15) ----
        {
            const float* z0 = zbuf + b_l * 68 + j_l;
            const float* z1 = zbuf + 1088 + b_l * 68 + j_l;
            const float* xb = xzs + par * 1088 + j_l * 17 + b_l;
            float zv1 = z0[0]  + z1[0]  + xb[0];
            float zv2 = z0[16] + z1[16] + xb[272];
            float zv3 = z0[32] + z1[32] + xb[544];
            float zv4 = z0[48] + z1[48] + xb[816];
            float v1 = ftanh(zv1);
            float v2 = fsig(zv2);
            float v3 = fsig(zv3);
            float v4 = fsig(zv4);
            c_state = v1 * v2 + v3 * c_state;
            float hnew = v4 * ftanh(c_state);
            __stcg(&g_h[par ^ 1][b0 + b_l][u0 + j_l], hnew);
        }

        // ---- barrier: two-level arrive early, stage xz, poll ----
        __syncthreads();
        if (tid == 0) {
            unsigned ps = atom_add_acqrel(subp, 1u);
            if ((ps & 3u) == 3u) {
                unsigned pm = atom_add_acqrel(master, 1u);
                if ((pm & 7u) == 7u)
                    st_release(gen, (unsigned)(t + 1));
            }
        }
        if (t + 1 < TSTEPS) {
            float vv[4] = {xnext.x, xnext.y, xnext.z, xnext.w};
            float* dst = xzs + ((t + 1) & 1) * 1088;
#pragma unroll
            for (int j = 0; j < 4; j++)
                dst[pg * 272 + (pq * 4 + j) * 17 + pb] = vv[j];
        }
        if (tid == 0) {
            while (ld_acquire(gen) < (unsigned)(t + 1)) { }
        }
        __syncthreads();
    }
}

// ---- final dense + softmax --------------------------------------------------
__global__ void fc_softmax(const float* __restrict__ fc_w,
                           const float* __restrict__ fc_b,
                           float* __restrict__ out)
{
    const int b = blockIdx.x;
    const int l = threadIdx.x;
    float a0 = 0.f, a1 = 0.f, a2 = 0.f, a3 = 0.f;
    const float* hg = &g_h[0][b][0];   // t=1023 wrote parity 0
    for (int k = l * 16; k < l * 16 + 16; k += 4) {
        float4 hv = *(const float4*)(hg + k);
        float hx[4] = {hv.x, hv.y, hv.z, hv.w};
#pragma unroll
        for (int q = 0; q < 4; q++) {
            float4 wv = *(const float4*)&fc_w[(k + q) * 4];
            a0 += hx[q] * wv.x; a1 += hx[q] * wv.y;
            a2 += hx[q] * wv.z; a3 += hx[q] * wv.w;
        }
    }
#pragma unroll
    for (int o = 16; o > 0; o >>= 1) {
        a0 += __shfl_down_sync(0xffffffffu, a0, o);
        a1 += __shfl_down_sync(0xffffffffu, a1, o);
        a2 += __shfl_down_sync(0xffffffffu, a2, o);
        a3 += __shfl_down_sync(0xffffffffu, a3, o);
    }
    if (l == 0) {
        float z0 = a0 + fc_b[0], z1 = a1 + fc_b[1];
        float z2 = a2 + fc_b[2], z3 = a3 + fc_b[3];
        float m = fmaxf(fmaxf(z0, z1), fmaxf(z2, z3));
        float e0 = __expf(z0 - m), e1 = __expf(z1 - m);
        float e2 = __expf(z2 - m), e3 = __expf(z3 - m);
        float inv = __fdividef(1.f, e0 + e1 + e2 + e3);
        out[b * 4 + 0] = e0 * inv;
        out[b * 4 + 1] = e1 * inv;
        out[b * 4 + 2] = e2 * inv;
        out[b * 4 + 3] = e3 * inv;
    }
}

// ---------------------------------------------------------------------------
extern "C" void kernel_launch(void* const* d_in, const int* in_sizes, int n_in,
                              void* d_out, int out_size)
{
    const float* tx      = (const float*)d_in[0];
    const float* kernelW = (const float*)d_in[1];
    const float* R       = (const float*)d_in[2];
    const float* bias    = (const float*)d_in[3];
    const float* fc_w    = (const float*)d_in[4];
    const float* fc_b    = (const float*)d_in[5];
    float* out           = (float*)d_out;

    cudaFuncSetAttribute(lstm_recur,
                         cudaFuncAttributeMaxDynamicSharedMemorySize, SM_BYTES);

    init_kernel<<<(2 * BATCH * UNITS + 255) / 256, 256>>>();
    prep_A<<<16384, 256>>>(tx);
    prep_W<<<256, 256>>>(kernelW);
    gemm_mma<<<dim3(16, 512), 256>>>(bias);
    lstm_recur<<<NCTA, TPB, SM_BYTES>>>(R);
    fc_softmax<<<BATCH, 32>>>(fc_w, fc_b, out);
    (void)in_sizes; (void)n_in; (void)out_size;
}

// round 15
// speedup vs baseline: 1.3712x; 1.2862x over previous
#include <cuda_runtime.h>
#include <cuda_bf16.h>
#include <cstdint>

// LSTM  B=64, T=1024, D=512, U=512, OUT=4
#define BATCH    64
#define TSTEPS   1024
#define DIN      512
#define UNITS    512
#define FOURU    2048
#define NCTA     128
#define TPB      256
#define NBG      4
#define GROUP_CTAS 32
#define NMTILE   4096
#define NKSTEP   32

// recurrence smem offsets (bytes)
#define SM_BHI   0            // bf16 [64 n][520]     : 66560
#define SM_BLO   66560        // bf16 [64 n][520]     : 66560
#define SM_AHI   133120       // bf16 [16 b][520]     : 16640
#define SM_ALO   149760       // bf16 [16 b][520]     : 16640
#define SM_Z     166400       // f32  [2][16 b][68]   : 8704
#define SM_XZ    175104       // f32  [2][1088]       : 8704
#define SM_BYTES 183808

__device__ float    g_xz[(size_t)BATCH * TSTEPS * FOURU];
__device__ uint4    g_Afrag[(size_t)NMTILE * NKSTEP * 2 * 32];
__device__ uint4    g_Wfrag[(size_t)NKSTEP * 2 * 64 * 32 * 2];
__device__ float    g_h[2][BATCH][UNITS];        // batch-major
__device__ unsigned g_arrive[NBG * 32];
__device__ unsigned g_gen[NBG * 32];

__device__ __forceinline__ float fsig(float x) {
    return __fdividef(1.f, 1.f + __expf(-x));
}
__device__ __forceinline__ float ftanh(float x) {
    return 1.f - __fdividef(2.f, __expf(2.f * x) + 1.f);
}
__device__ __forceinline__ unsigned atom_add_acqrel(unsigned* p, unsigned v) {
    unsigned old;
    asm volatile("atom.acq_rel.gpu.global.add.u32 %0, [%1], %2;"
                 : "=r"(old) : "l"(p), "r"(v) : "memory");
    return old;
}
__device__ __forceinline__ void st_release(unsigned* p, unsigned v) {
    asm volatile("st.release.gpu.global.u32 [%0], %1;" :: "l"(p), "r"(v) : "memory");
}
__device__ __forceinline__ unsigned ld_acquire(const unsigned* p) {
    unsigned v;
    asm volatile("ld.acquire.gpu.global.u32 %0, [%1];" : "=r"(v) : "l"(p) : "memory");
    return v;
}
__device__ __forceinline__ uint32_t pack_split_hi(float a, float b) {
    __nv_bfloat16 ha = __float2bfloat16(a), hb = __float2bfloat16(b);
    return (uint32_t)*(uint16_t*)&ha | ((uint32_t)*(uint16_t*)&hb << 16);
}
__device__ __forceinline__ uint32_t pack_split_lo(float a, float b) {
    __nv_bfloat16 ha = __float2bfloat16(a), hb = __float2bfloat16(b);
    __nv_bfloat16 la = __float2bfloat16(a - __bfloat162float(ha));
    __nv_bfloat16 lb = __float2bfloat16(b - __bfloat162float(hb));
    return (uint32_t)*(uint16_t*)&la | ((uint32_t)*(uint16_t*)&lb << 16);
}
__device__ __forceinline__ uint32_t smem_u32(const void* p) {
    return (uint32_t)__cvta_generic_to_shared(p);
}

__global__ void init_kernel() {
    int i = blockIdx.x * blockDim.x + threadIdx.x;
    if (i < 2 * BATCH * UNITS) ((float*)g_h)[i] = 0.f;
    if (i < NBG * 32) { g_arrive[i] = 0u; g_gen[i] = 0u; }
}

// ---- prep A (unchanged) ----------------------------------------------------
__global__ __launch_bounds__(256) void prep_A(const float* __restrict__ A) {
    int f = blockIdx.x * 256 + threadIdx.x;
    int t = f & 31, ks = (f >> 5) & 31, mt = f >> 10;
    uint32_t hi[4], lo[4];
#pragma unroll
    for (int r = 0; r < 4; r++) {
        int m  = mt * 16 + (r & 1) * 8 + (t >> 2);
        int k0 = ks * 16 + ((r & 2) << 2) + ((t & 3) << 1);
        float2 av = *(const float2*)(A + (size_t)m * DIN + k0);
        hi[r] = pack_split_hi(av.x, av.y);
        lo[r] = pack_split_lo(av.x, av.y);
    }
    size_t ib = ((size_t)mt * 32 + ks) * 2;
    g_Afrag[ib * 32 + t]       = make_uint4(hi[0], hi[1], hi[2], hi[3]);
    g_Afrag[(ib + 1) * 32 + t] = make_uint4(lo[0], lo[1], lo[2], lo[3]);
}

// ---- prep W (unchanged) ----------------------------------------------------
__global__ __launch_bounds__(256) void prep_W(const float* __restrict__ W) {
    int f = blockIdx.x * 256 + threadIdx.x;
    int t = f & 31, ngrp = (f >> 5) & 63, ks = f >> 11;
    uint32_t hi[8], lo[8];
#pragma unroll
    for (int nblk = 0; nblk < 4; nblk++)
#pragma unroll
        for (int reg = 0; reg < 2; reg++) {
            int k0 = ks * 16 + reg * 8 + (t & 3) * 2;
            int n  = ngrp * 32 + nblk * 8 + (t >> 2);
            float w0 = W[(size_t)k0 * FOURU + n];
            float w1 = W[(size_t)(k0 + 1) * FOURU + n];
            hi[nblk * 2 + reg] = pack_split_hi(w0, w1);
            lo[nblk * 2 + reg] = pack_split_lo(w0, w1);
        }
    size_t wb = (((size_t)ks * 2 + 0) * 64 + ngrp) * 32 + t;
    size_t wl = (((size_t)ks * 2 + 1) * 64 + ngrp) * 32 + t;
    g_Wfrag[wb * 2]     = make_uint4(hi[0], hi[1], hi[2], hi[3]);
    g_Wfrag[wb * 2 + 1] = make_uint4(hi[4], hi[5], hi[6], hi[7]);
    g_Wfrag[wl * 2]     = make_uint4(lo[0], lo[1], lo[2], lo[3]);
    g_Wfrag[wl * 2 + 1] = make_uint4(lo[4], lo[5], lo[6], lo[7]);
}

#define MMA16816(c, a, b0v, b1v)                                              \
    asm volatile(                                                             \
        "mma.sync.aligned.m16n8k16.row.col.f32.bf16.bf16.f32 "                \
        "{%0,%1,%2,%3}, {%4,%5,%6,%7}, {%8,%9}, {%0,%1,%2,%3};"               \
        : "+f"((c)[0]), "+f"((c)[1]), "+f"((c)[2]), "+f"((c)[3])              \
        : "r"((a).x), "r"((a).y), "r"((a).z), "r"((a).w),                     \
          "r"(b0v), "r"(b1v))

#define LDSM4(r, addr)                                                        \
    asm volatile("ldmatrix.sync.aligned.m8n8.x4.shared.b16 "                  \
                 "{%0,%1,%2,%3}, [%4];"                                       \
                 : "=r"((r).x), "=r"((r).y), "=r"((r).z), "=r"((r).w)         \
                 : "r"(addr))

// ---- xz GEMM: __launch_bounds__(256,2) -> 2 CTAs/SM for latency overlap ----
__global__ __launch_bounds__(256, 2) void gemm_mma(const float* __restrict__ bias) {
    const int tid = threadIdx.x;
    const int t = tid & 31, wid = tid >> 5;
    const int wm = wid & 1, wn = wid >> 1;
    const int mtb = blockIdx.y * 8 + wm * 4;
    const int ngrp = blockIdx.x * 4 + wn;

    float acc[4][4][4];
#pragma unroll
    for (int mi = 0; mi < 4; mi++)
#pragma unroll
        for (int ni = 0; ni < 4; ni++)
#pragma unroll
            for (int c = 0; c < 4; c++) acc[mi][ni][c] = 0.f;

#pragma unroll 2
    for (int ks = 0; ks < NKSTEP; ks++) {
        uint4 ah[4], al[4];
#pragma unroll
        for (int mi = 0; mi < 4; mi++) {
            size_t ib = ((size_t)(mtb + mi) * 32 + ks) * 2;
            ah[mi] = g_Afrag[ib * 32 + t];
            al[mi] = g_Afrag[(ib + 1) * 32 + t];
        }
        size_t wb = (((size_t)ks * 2 + 0) * 64 + ngrp) * 32 + t;
        size_t wl = (((size_t)ks * 2 + 1) * 64 + ngrp) * 32 + t;
        uint4 bh0 = g_Wfrag[wb * 2], bh1 = g_Wfrag[wb * 2 + 1];
        uint4 bl0 = g_Wfrag[wl * 2], bl1 = g_Wfrag[wl * 2 + 1];
        uint32_t bh[8] = {bh0.x, bh0.y, bh0.z, bh0.w, bh1.x, bh1.y, bh1.z, bh1.w};
        uint32_t bl[8] = {bl0.x, bl0.y, bl0.z, bl0.w, bl1.x, bl1.y, bl1.z, bl1.w};

#pragma unroll
        for (int mi = 0; mi < 4; mi++)
#pragma unroll
            for (int ni = 0; ni < 4; ni++) {
                MMA16816(acc[mi][ni], ah[mi], bh[ni * 2], bh[ni * 2 + 1]);
                MMA16816(acc[mi][ni], ah[mi], bl[ni * 2], bl[ni * 2 + 1]);
                MMA16816(acc[mi][ni], al[mi], bh[ni * 2], bh[ni * 2 + 1]);
            }
    }

    const int colbase = blockIdx.x * 128 + wn * 32 + (t & 3) * 2;
    const int rowbase = blockIdx.y * 128 + wm * 64 + (t >> 2);
    float2 bv[4];
#pragma unroll
    for (int ni = 0; ni < 4; ni++)
        bv[ni] = *(const float2*)(bias + colbase + ni * 8);
#pragma unroll
    for (int mi = 0; mi < 4; mi++) {
        int r0 = rowbase + mi * 16;
#pragma unroll
        for (int ni = 0; ni < 4; ni++) {
            int col = colbase + ni * 8;
            float2 o0 = make_float2(acc[mi][ni][0] + bv[ni].x,
                                    acc[mi][ni][1] + bv[ni].y);
            float2 o1 = make_float2(acc[mi][ni][2] + bv[ni].x,
                                    acc[mi][ni][3] + bv[ni].y);
            __stcs((float2*)(g_xz + (size_t)r0 * FOURU + col), o0);
            __stcs((float2*)(g_xz + (size_t)(r0 + 8) * FOURU + col), o1);
        }
    }
}

// ---- persistent LSTM recurrence (R12 verbatim) -----------------------------
__global__ __launch_bounds__(TPB, 1) void lstm_recur(const float* __restrict__ R)
{
    extern __shared__ char smc[];
    __nv_bfloat16* Bhi = (__nv_bfloat16*)(smc + SM_BHI);
    __nv_bfloat16* Blo = (__nv_bfloat16*)(smc + SM_BLO);
    uint32_t* AhiW = (uint32_t*)(smc + SM_AHI);
    uint32_t* AloW = (uint32_t*)(smc + SM_ALO);
    float* zbuf = (float*)(smc + SM_Z);       // [2][16][68]
    float* xzs  = (float*)(smc + SM_XZ);

    const int tid = threadIdx.x;
    const int wid = tid >> 5, lane = tid & 31;
    const int ug = blockIdx.x >> 2, bg = blockIdx.x & 3;
    const int u0 = ug * 16, b0 = bg * 16;

    // ---- build B (R slice) once: B[n][k] = R[k][g*512+u0+j], n = g*16+j ----
    for (int i = tid; i < 64 * 512; i += TPB) {
        int k = i & 511, n = i >> 9;
        int g = n >> 4, j = n & 15;
        float v = R[(size_t)k * FOURU + g * UNITS + u0 + j];
        __nv_bfloat16 hb = __float2bfloat16(v);
        __nv_bfloat16 lb = __float2bfloat16(v - __bfloat162float(hb));
        Bhi[n * 520 + k] = hb;
        Blo[n * 520 + k] = lb;
    }

    // ---- xz staging map: thread -> (pb, pg, pq) ----------------------------
    const int pb = tid >> 4, pg = (tid >> 2) & 3, pq = tid & 3;
    const float* xz_thread = g_xz + (size_t)(b0 + pb) * TSTEPS * FOURU
                             + pg * UNITS + u0 + pq * 4;
    {
        float4 v = __ldcs((const float4*)xz_thread);
        float vv[4] = {v.x, v.y, v.z, v.w};
#pragma unroll
        for (int j = 0; j < 4; j++)
            xzs[pg * 272 + (pq * 4 + j) * 17 + pb] = vv[j];
    }
    __syncthreads();

    // ---- lane-invariant LDSM addresses -------------------------------------
    const int khalf = wid >> 2, npair = wid & 3;
    const int aRow = (lane & 7) + ((lane >> 3) & 1) * 8;
    const int aKof = ((lane >> 4) & 1) * 16;            // bytes
    const uint32_t aHiAddr = smem_u32(smc + SM_AHI) + aRow * 1040 + aKof;
    const uint32_t aLoAddr = smem_u32(smc + SM_ALO) + aRow * 1040 + aKof;
    const int bRow = npair * 16 + ((lane >> 4) & 1) * 8 + (lane & 7);
    const int bKof = ((lane >> 3) & 1) * 16;
    const uint32_t bHiAddr = smem_u32(smc + SM_BHI) + bRow * 1040 + bKof;
    const uint32_t bLoAddr = smem_u32(smc + SM_BLO) + bRow * 1040 + bKof;

    // ---- preload this warp's B-hi fragments into registers (time-invariant)
    uint4 Bh[16];
#pragma unroll
    for (int i = 0; i < 16; i++)
        LDSM4(Bh[i], bHiAddr + (khalf * 16 + i) * 32);

    // A-staging map: b = tid>>4, 8 chunks of 4 floats at u = (tid&15)*4+q*64
    const int sb = tid >> 4, su = (tid & 15) * 4;
    // gates map (coalesced h writeback): b = tid>>4, u = tid&15
    const int b_l = tid >> 4, j_l = tid & 15;

    unsigned* arrive = &g_arrive[bg * 32];
    unsigned* gen    = &g_gen[bg * 32];

    float c_state = 0.f;

    for (int t = 0; t < TSTEPS; t++) {
        const int par = t & 1;
        float4 xnext = make_float4(0.f, 0.f, 0.f, 0.f);
        if (t + 1 < TSTEPS)
            xnext = __ldcs((const float4*)(xz_thread + (size_t)(t + 1) * FOURU));

        // ---- stage A = h(t)[16 b][512 k] as split bf16 ----
        const float* hsrc = &g_h[par][b0 + sb][0];
#pragma unroll
        for (int q = 0; q < 8; q++) {
            int u = su + q * 64;
            float4 v = __ldcg((const float4*)(hsrc + u));
            uint32_t h01, h23, l01, l23;
            asm("cvt.rn.bf16x2.f32 %0, %1, %2;" : "=r"(h01) : "f"(v.y), "f"(v.x));
            asm("cvt.rn.bf16x2.f32 %0, %1, %2;" : "=r"(h23) : "f"(v.w), "f"(v.z));
            float f0 = __uint_as_float(h01 << 16);
            float f1 = __uint_as_float(h01 & 0xffff0000u);
            float f2 = __uint_as_float(h23 << 16);
            float f3 = __uint_as_float(h23 & 0xffff0000u);
            asm("cvt.rn.bf16x2.f32 %0, %1, %2;"
                : "=r"(l01) : "f"(v.y - f1), "f"(v.x - f0));
            asm("cvt.rn.bf16x2.f32 %0, %1, %2;"
                : "=r"(l23) : "f"(v.w - f3), "f"(v.z - f2));
            int w = sb * 260 + u / 2;
            AhiW[w] = h01; AhiW[w + 1] = h23;
            AloW[w] = l01; AloW[w + 1] = l23;
        }
        __syncthreads();

        // ---- MMA: n-tiles {2*npair, 2*npair+1}, k-half khalf ----
        float acc0[4] = {0.f, 0.f, 0.f, 0.f};
        float acc1[4] = {0.f, 0.f, 0.f, 0.f};
#pragma unroll
        for (int i = 0; i < 16; i++) {
            uint32_t ofs = (khalf * 16 + i) * 32;
            uint4 ah, al, bl;
            LDSM4(ah, aHiAddr + ofs);
            LDSM4(al, aLoAddr + ofs);
            LDSM4(bl, bLoAddr + ofs);
            MMA16816(acc0, ah, Bh[i].x, Bh[i].y);
            MMA16816(acc1, ah, Bh[i].z, Bh[i].w);
            MMA16816(acc0, ah, bl.x, bl.y);
            MMA16816(acc1, ah, bl.z, bl.w);
            MMA16816(acc0, al, Bh[i].x, Bh[i].y);
            MMA16816(acc1, al, Bh[i].z, Bh[i].w);
        }

        // ---- both halves write partial z to their own buffer ----
        {
            float* zb = zbuf + khalf * 1088;
            int ra = lane >> 2, cb = (lane & 3) * 2;
            int n0 = npair * 16 + cb, n1 = npair * 16 + 8 + cb;
            *(float2*)&zb[ra * 68 + n0]       = make_float2(acc0[0], acc0[1]);
            *(float2*)&zb[(ra + 8) * 68 + n0] = make_float2(acc0[2], acc0[3]);
            *(float2*)&zb[ra * 68 + n1]       = make_float2(acc1[0], acc1[1]);
            *(float2*)&zb[(ra + 8) * 68 + n1] = make_float2(acc1[2], acc1[3]);
        }
        __syncthreads();

        // ---- gates: thread (b_l = tid>>4, j_l = tid&15) ----
        {
            const float* z0 = zbuf + b_l * 68 + j_l;
            const float* z1 = zbuf + 1088 + b_l * 68 + j_l;
            const float* xb = xzs + par * 1088 + j_l * 17 + b_l;
            float zv1 = z0[0]  + z1[0]  + xb[0];
            float zv2 = z0[16] + z1[16] + xb[272];
            float zv3 = z0[32] + z1[32] + xb[544];
            float zv4 = z0[48] + z1[48] + xb[816];
            float v1 = ftanh(zv1);
            float v2 = fsig(zv2);
            float v3 = fsig(zv3);
            float v4 = fsig(zv4);
            c_state = v1 * v2 + v3 * c_state;
            float hnew = v4 * ftanh(c_state);
            __stcg(&g_h[par ^ 1][b0 + b_l][u0 + j_l], hnew);
        }

        // ---- barrier: arrive early, stage xz, poll ----
        __syncthreads();
        if (tid == 0) {
            unsigned prev = atom_add_acqrel(arrive, 1u);
            if ((prev & 31u) == 31u)
                st_release(gen, (unsigned)(t + 1));
        }
        if (t + 1 < TSTEPS) {
            float vv[4] = {xnext.x, xnext.y, xnext.z, xnext.w};
            float* dst = xzs + ((t + 1) & 1) * 1088;
#pragma unroll
            for (int j = 0; j < 4; j++)
                dst[pg * 272 + (pq * 4 + j) * 17 + pb] = vv[j];
        }
        if (tid == 0) {
            while (ld_acquire(gen) < (unsigned)(t + 1)) { }
        }
        __syncthreads();
    }
}

// ---- final dense + softmax --------------------------------------------------
__global__ void fc_softmax(const float* __restrict__ fc_w,
                           const float* __restrict__ fc_b,
                           float* __restrict__ out)
{
    const int b = blockIdx.x;
    const int l = threadIdx.x;
    float a0 = 0.f, a1 = 0.f, a2 = 0.f, a3 = 0.f;
    const float* hg = &g_h[0][b][0];   // t=1023 wrote parity 0
    for (int k = l * 16; k < l * 16 + 16; k += 4) {
        float4 hv = *(const float4*)(hg + k);
        float hx[4] = {hv.x, hv.y, hv.z, hv.w};
#pragma unroll
        for (int q = 0; q < 4; q++) {
            float4 wv = *(const float4*)&fc_w[(k + q) * 4];
            a0 += hx[q] * wv.x; a1 += hx[q] * wv.y;
            a2 += hx[q] * wv.z; a3 += hx[q] * wv.w;
        }
    }
#pragma unroll
    for (int o = 16; o > 0; o >>= 1) {
        a0 += __shfl_down_sync(0xffffffffu, a0, o);
        a1 += __shfl_down_sync(0xffffffffu, a1, o);
        a2 += __shfl_down_sync(0xffffffffu, a2, o);
        a3 += __shfl_down_sync(0xffffffffu, a3, o);
    }
    if (l == 0) {
        float z0 = a0 + fc_b[0], z1 = a1 + fc_b[1];
        float z2 = a2 + fc_b[2], z3 = a3 + fc_b[3];
        float m = fmaxf(fmaxf(z0, z1), fmaxf(z2, z3));
        float e0 = __expf(z0 - m), e1 = __expf(z1 - m);
        float e2 = __expf(z2 - m), e3 = __expf(z3 - m);
        float inv = __fdividef(1.f, e0 + e1 + e2 + e3);
        out[b * 4 + 0] = e0 * inv;
        out[b * 4 + 1] = e1 * inv;
        out[b * 4 + 2] = e2 * inv;
        out[b * 4 + 3] = e3 * inv;
    }
}

// ---------------------------------------------------------------------------
extern "C" void kernel_launch(void* const* d_in, const int* in_sizes, int n_in,
                              void* d_out, int out_size)
{
    const float* tx      = (const float*)d_in[0];
    const float* kernelW = (const float*)d_in[1];
    const float* R       = (const float*)d_in[2];
    const float* bias    = (const float*)d_in[3];
    const float* fc_w    = (const float*)d_in[4];
    const float* fc_b    = (const float*)d_in[5];
    float* out           = (float*)d_out;

    cudaFuncSetAttribute(lstm_recur,
                         cudaFuncAttributeMaxDynamicSharedMemorySize, SM_BYTES);

    init_kernel<<<(2 * BATCH * UNITS + 255) / 256, 256>>>();
    prep_A<<<16384, 256>>>(tx);
    prep_W<<<256, 256>>>(kernelW);
    gemm_mma<<<dim3(16, 512), 256>>>(bias);
    lstm_recur<<<NCTA, TPB, SM_BYTES>>>(R);
    fc_softmax<<<BATCH, 32>>>(fc_w, fc_b, out);
    (void)in_sizes; (void)n_in; (void)out_size;
}

// round 16
// speedup vs baseline: 1.5597x; 1.1375x over previous
#include <cuda_runtime.h>
#include <cuda_fp16.h>
#include <cstdint>

// LSTM  B=64, T=1024, D=512, U=512, OUT=4
#define BATCH    64
#define TSTEPS   1024
#define DIN      512
#define UNITS    512
#define FOURU    2048
#define NCTA     128
#define TPB      256
#define NBG      4
#define GROUP_CTAS 32
#define NMTILE   4096
#define NKSTEP   32

// recurrence smem offsets (bytes)
#define SM_BHI   0            // f16 [64 n][520]      : 66560
#define SM_BLO   66560        // f16 [64 n][520]      : 66560
#define SM_AHI   133120       // f16 [16 b][520]      : 16640
#define SM_Z     149760       // f32 [2][16 b][68]    : 8704
#define SM_XZ    158464       // f32 [2][1088]        : 8704
#define SM_BYTES 167168

__device__ float    g_xz[(size_t)BATCH * TSTEPS * FOURU];
__device__ uint4    g_Afrag[(size_t)NMTILE * NKSTEP * 32];       // hi only
__device__ uint4    g_Wfrag[(size_t)NKSTEP * 2 * 64 * 32 * 2];   // hi+lo
__device__ float    g_h[2][BATCH][UNITS];        // batch-major
__device__ unsigned g_arrive[NBG * 32];
__device__ unsigned g_gen[NBG * 32];

__device__ __forceinline__ float fsig(float x) {
    return __fdividef(1.f, 1.f + __expf(-x));
}
__device__ __forceinline__ float ftanh(float x) {
    return 1.f - __fdividef(2.f, __expf(2.f * x) + 1.f);
}
__device__ __forceinline__ unsigned atom_add_acqrel(unsigned* p, unsigned v) {
    unsigned old;
    asm volatile("atom.acq_rel.gpu.global.add.u32 %0, [%1], %2;"
                 : "=r"(old) : "l"(p), "r"(v) : "memory");
    return old;
}
__device__ __forceinline__ void st_release(unsigned* p, unsigned v) {
    asm volatile("st.release.gpu.global.u32 [%0], %1;" :: "l"(p), "r"(v) : "memory");
}
__device__ __forceinline__ unsigned ld_acquire(const unsigned* p) {
    unsigned v;
    asm volatile("ld.acquire.gpu.global.u32 %0, [%1];" : "=r"(v) : "l"(p) : "memory");
    return v;
}
__device__ __forceinline__ uint32_t pack_h_hi(float a, float b) {
    __half ha = __float2half_rn(a), hb = __float2half_rn(b);
    return (uint32_t)*(uint16_t*)&ha | ((uint32_t)*(uint16_t*)&hb << 16);
}
__device__ __forceinline__ uint32_t pack_h_lo(float a, float b) {
    __half ha = __float2half_rn(a), hb = __float2half_rn(b);
    __half la = __float2half_rn(a - __half2float(ha));
    __half lb = __float2half_rn(b - __half2float(hb));
    return (uint32_t)*(uint16_t*)&la | ((uint32_t)*(uint16_t*)&lb << 16);
}
__device__ __forceinline__ uint32_t smem_u32(const void* p) {
    return (uint32_t)__cvta_generic_to_shared(p);
}

__global__ void init_kernel() {
    int i = blockIdx.x * blockDim.x + threadIdx.x;
    if (i < 2 * BATCH * UNITS) ((float*)g_h)[i] = 0.f;
    if (i < NBG * 32) { g_arrive[i] = 0u; g_gen[i] = 0u; }
}

// ---- prep A: fp16 hi fragments only ----------------------------------------
__global__ __launch_bounds__(256) void prep_A(const float* __restrict__ A) {
    int f = blockIdx.x * 256 + threadIdx.x;
    int t = f & 31, ks = (f >> 5) & 31, mt = f >> 10;
    uint32_t hi[4];
#pragma unroll
    for (int r = 0; r < 4; r++) {
        int m  = mt * 16 + (r & 1) * 8 + (t >> 2);
        int k0 = ks * 16 + ((r & 2) << 2) + ((t & 3) << 1);
        float2 av = *(const float2*)(A + (size_t)m * DIN + k0);
        hi[r] = pack_h_hi(av.x, av.y);
    }
    g_Afrag[((size_t)mt * 32 + ks) * 32 + t] = make_uint4(hi[0], hi[1], hi[2], hi[3]);
}

// ---- prep W: fp16 hi+lo fragments ------------------------------------------
__global__ __launch_bounds__(256) void prep_W(const float* __restrict__ W) {
    int f = blockIdx.x * 256 + threadIdx.x;
    int t = f & 31, ngrp = (f >> 5) & 63, ks = f >> 11;
    uint32_t hi[8], lo[8];
#pragma unroll
    for (int nblk = 0; nblk < 4; nblk++)
#pragma unroll
        for (int reg = 0; reg < 2; reg++) {
            int k0 = ks * 16 + reg * 8 + (t & 3) * 2;
            int n  = ngrp * 32 + nblk * 8 + (t >> 2);
            float w0 = W[(size_t)k0 * FOURU + n];
            float w1 = W[(size_t)(k0 + 1) * FOURU + n];
            hi[nblk * 2 + reg] = pack_h_hi(w0, w1);
            lo[nblk * 2 + reg] = pack_h_lo(w0, w1);
        }
    size_t wb = (((size_t)ks * 2 + 0) * 64 + ngrp) * 32 + t;
    size_t wl = (((size_t)ks * 2 + 1) * 64 + ngrp) * 32 + t;
    g_Wfrag[wb * 2]     = make_uint4(hi[0], hi[1], hi[2], hi[3]);
    g_Wfrag[wb * 2 + 1] = make_uint4(hi[4], hi[5], hi[6], hi[7]);
    g_Wfrag[wl * 2]     = make_uint4(lo[0], lo[1], lo[2], lo[3]);
    g_Wfrag[wl * 2 + 1] = make_uint4(lo[4], lo[5], lo[6], lo[7]);
}

#define MMA16816(c, a, b0v, b1v)                                              \
    asm volatile(                                                             \
        "mma.sync.aligned.m16n8k16.row.col.f32.f16.f16.f32 "                  \
        "{%0,%1,%2,%3}, {%4,%5,%6,%7}, {%8,%9}, {%0,%1,%2,%3};"               \
        : "+f"((c)[0]), "+f"((c)[1]), "+f"((c)[2]), "+f"((c)[3])              \
        : "r"((a).x), "r"((a).y), "r"((a).z), "r"((a).w),                     \
          "r"(b0v), "r"(b1v))

#define LDSM4(r, addr)                                                        \
    asm volatile("ldmatrix.sync.aligned.m8n8.x4.shared.b16 "                  \
                 "{%0,%1,%2,%3}, [%4];"                                       \
                 : "=r"((r).x), "=r"((r).y), "=r"((r).z), "=r"((r).w)         \
                 : "r"(addr))

// ---- xz GEMM: fp16 2-term (Ah*Wh + Ah*Wl), 2 CTAs/SM -----------------------
__global__ __launch_bounds__(256, 2) void gemm_mma(const float* __restrict__ bias) {
    const int tid = threadIdx.x;
    const int t = tid & 31, wid = tid >> 5;
    const int wm = wid & 1, wn = wid >> 1;
    const int mtb = blockIdx.y * 8 + wm * 4;
    const int ngrp = blockIdx.x * 4 + wn;

    float acc[4][4][4];
#pragma unroll
    for (int mi = 0; mi < 4; mi++)
#pragma unroll
        for (int ni = 0; ni < 4; ni++)
#pragma unroll
            for (int c = 0; c < 4; c++) acc[mi][ni][c] = 0.f;

#pragma unroll 2
    for (int ks = 0; ks < NKSTEP; ks++) {
        uint4 ah[4];
#pragma unroll
        for (int mi = 0; mi < 4; mi++)
            ah[mi] = g_Afrag[((size_t)(mtb + mi) * 32 + ks) * 32 + t];
        size_t wb = (((size_t)ks * 2 + 0) * 64 + ngrp) * 32 + t;
        size_t wl = (((size_t)ks * 2 + 1) * 64 + ngrp) * 32 + t;
        uint4 bh0 = g_Wfrag[wb * 2], bh1 = g_Wfrag[wb * 2 + 1];
        uint4 bl0 = g_Wfrag[wl * 2], bl1 = g_Wfrag[wl * 2 + 1];
        uint32_t bh[8] = {bh0.x, bh0.y, bh0.z, bh0.w, bh1.x, bh1.y, bh1.z, bh1.w};
        uint32_t bl[8] = {bl0.x, bl0.y, bl0.z, bl0.w, bl1.x, bl1.y, bl1.z, bl1.w};

#pragma unroll
        for (int mi = 0; mi < 4; mi++)
#pragma unroll
            for (int ni = 0; ni < 4; ni++) {
                MMA16816(acc[mi][ni], ah[mi], bh[ni * 2], bh[ni * 2 + 1]);
                MMA16816(acc[mi][ni], ah[mi], bl[ni * 2], bl[ni * 2 + 1]);
            }
    }

    const int colbase = blockIdx.x * 128 + wn * 32 + (t & 3) * 2;
    const int rowbase = blockIdx.y * 128 + wm * 64 + (t >> 2);
    float2 bv[4];
#pragma unroll
    for (int ni = 0; ni < 4; ni++)
        bv[ni] = *(const float2*)(bias + colbase + ni * 8);
#pragma unroll
    for (int mi = 0; mi < 4; mi++) {
        int r0 = rowbase + mi * 16;
#pragma unroll
        for (int ni = 0; ni < 4; ni++) {
            int col = colbase + ni * 8;
            float2 o0 = make_float2(acc[mi][ni][0] + bv[ni].x,
                                    acc[mi][ni][1] + bv[ni].y);
            float2 o1 = make_float2(acc[mi][ni][2] + bv[ni].x,
                                    acc[mi][ni][3] + bv[ni].y);
            __stcs((float2*)(g_xz + (size_t)r0 * FOURU + col), o0);
            __stcs((float2*)(g_xz + (size_t)(r0 + 8) * FOURU + col), o1);
        }
    }
}

// ---- persistent LSTM recurrence: fp16 2-term (Ah*Bh + Ah*Bl) ---------------
__global__ __launch_bounds__(TPB, 1) void lstm_recur(const float* __restrict__ R)
{
    extern __shared__ char smc[];
    __half* Bhi = (__half*)(smc + SM_BHI);
    __half* Blo = (__half*)(smc + SM_BLO);
    uint32_t* AhiW = (uint32_t*)(smc + SM_AHI);
    float* zbuf = (float*)(smc + SM_Z);       // [2][16][68]
    float* xzs  = (float*)(smc + SM_XZ);

    const int tid = threadIdx.x;
    const int wid = tid >> 5, lane = tid & 31;
    const int ug = blockIdx.x >> 2, bg = blockIdx.x & 3;
    const int u0 = ug * 16, b0 = bg * 16;

    // ---- build B (R slice) once: B[n][k] = R[k][g*512+u0+j], n = g*16+j ----
    for (int i = tid; i < 64 * 512; i += TPB) {
        int k = i & 511, n = i >> 9;
        int g = n >> 4, j = n & 15;
        float v = R[(size_t)k * FOURU + g * UNITS + u0 + j];
        __half hb = __float2half_rn(v);
        __half lb = __float2half_rn(v - __half2float(hb));
        Bhi[n * 520 + k] = hb;
        Blo[n * 520 + k] = lb;
    }

    // ---- xz staging map: thread -> (pb, pg, pq) ----------------------------
    const int pb = tid >> 4, pg = (tid >> 2) & 3, pq = tid & 3;
    const float* xz_thread = g_xz + (size_t)(b0 + pb) * TSTEPS * FOURU
                             + pg * UNITS + u0 + pq * 4;
    {
        float4 v = __ldcs((const float4*)xz_thread);
        float vv[4] = {v.x, v.y, v.z, v.w};
#pragma unroll
        for (int j = 0; j < 4; j++)
            xzs[pg * 272 + (pq * 4 + j) * 17 + pb] = vv[j];
    }
    __syncthreads();

    // ---- lane-invariant LDSM addresses -------------------------------------
    const int khalf = wid >> 2, npair = wid & 3;
    const int aRow = (lane & 7) + ((lane >> 3) & 1) * 8;
    const int aKof = ((lane >> 4) & 1) * 16;            // bytes
    const uint32_t aHiAddr = smem_u32(smc + SM_AHI) + aRow * 1040 + aKof;
    const int bRow = npair * 16 + ((lane >> 4) & 1) * 8 + (lane & 7);
    const int bKof = ((lane >> 3) & 1) * 16;
    const uint32_t bHiAddr = smem_u32(smc + SM_BHI) + bRow * 1040 + bKof;
    const uint32_t bLoAddr = smem_u32(smc + SM_BLO) + bRow * 1040 + bKof;

    // ---- preload this warp's B-hi fragments into registers (time-invariant)
    uint4 Bh[16];
#pragma unroll
    for (int i = 0; i < 16; i++)
        LDSM4(Bh[i], bHiAddr + (khalf * 16 + i) * 32);

    // A-staging map: b = tid>>4, 8 chunks of 4 floats at u = (tid&15)*4+q*64
    const int sb = tid >> 4, su = (tid & 15) * 4;
    // gates map (coalesced h writeback): b = tid>>4, u = tid&15
    const int b_l = tid >> 4, j_l = tid & 15;

    unsigned* arrive = &g_arrive[bg * 32];
    unsigned* gen    = &g_gen[bg * 32];

    float c_state = 0.f;

    for (int t = 0; t < TSTEPS; t++) {
        const int par = t & 1;
        float4 xnext = make_float4(0.f, 0.f, 0.f, 0.f);
        if (t + 1 < TSTEPS)
            xnext = __ldcs((const float4*)(xz_thread + (size_t)(t + 1) * FOURU));

        // ---- stage A = h(t)[16 b][512 k] as fp16 (hi only) ----
        const float* hsrc = &g_h[par][b0 + sb][0];
#pragma unroll
        for (int q = 0; q < 8; q++) {
            int u = su + q * 64;
            float4 v = __ldcg((const float4*)(hsrc + u));
            uint32_t h01, h23;
            asm("cvt.rn.f16x2.f32 %0, %1, %2;" : "=r"(h01) : "f"(v.y), "f"(v.x));
            asm("cvt.rn.f16x2.f32 %0, %1, %2;" : "=r"(h23) : "f"(v.w), "f"(v.z));
            int w = sb * 260 + u / 2;
            AhiW[w] = h01; AhiW[w + 1] = h23;
        }
        __syncthreads();

        // ---- MMA: n-tiles {2*npair, 2*npair+1}, k-half khalf ----
        float acc0[4] = {0.f, 0.f, 0.f, 0.f};
        float acc1[4] = {0.f, 0.f, 0.f, 0.f};
#pragma unroll
        for (int i = 0; i < 16; i++) {
            uint32_t ofs = (khalf * 16 + i) * 32;
            uint4 ah, bl;
            LDSM4(ah, aHiAddr + ofs);
            LDSM4(bl, bLoAddr + ofs);
            MMA16816(acc0, ah, Bh[i].x, Bh[i].y);
            MMA16816(acc1, ah, Bh[i].z, Bh[i].w);
            MMA16816(acc0, ah, bl.x, bl.y);
            MMA16816(acc1, ah, bl.z, bl.w);
        }

        // ---- both halves write partial z to their own buffer ----
        {
            float* zb = zbuf + khalf * 1088;
            int ra = lane >> 2, cb = (lane & 3) * 2;
            int n0 = npair * 16 + cb, n1 = npair * 16 + 8 + cb;
            *(float2*)&zb[ra * 68 + n0]       = make_float2(acc0[0], acc0[1]);
            *(float2*)&zb[(ra + 8) * 68 + n0] = make_float2(acc0[2], acc0[3]);
            *(float2*)&zb[ra * 68 + n1]       = make_float2(acc1[0], acc1[1]);
            *(float2*)&zb[(ra + 8) * 68 + n1] = make_float2(acc1[2], acc1[3]);
        }
        __syncthreads();

        // ---- gates: thread (b_l = tid>>4, j_l = tid&15) ----
        {
            const float* z0 = zbuf + b_l * 68 + j_l;
            const float* z1 = zbuf + 1088 + b_l * 68 + j_l;
            const float* xb = xzs + par * 1088 + j_l * 17 + b_l;
            float zv1 = z0[0]  + z1[0]  + xb[0];
            float zv2 = z0[16] + z1[16] + xb[272];
            float zv3 = z0[32] + z1[32] + xb[544];
            float zv4 = z0[48] + z1[48] + xb[816];
            float v1 = ftanh(zv1);
            float v2 = fsig(zv2);
            float v3 = fsig(zv3);
            float v4 = fsig(zv4);
            c_state = v1 * v2 + v3 * c_state;
            float hnew = v4 * ftanh(c_state);
            __stcg(&g_h[par ^ 1][b0 + b_l][u0 + j_l], hnew);
        }

        // ---- barrier: arrive early, stage xz, poll ----
        __syncthreads();
        if (tid == 0) {
            unsigned prev = atom_add_acqrel(arrive, 1u);
            if ((prev & 31u) == 31u)
                st_release(gen, (unsigned)(t + 1));
        }
        if (t + 1 < TSTEPS) {
            float vv[4] = {xnext.x, xnext.y, xnext.z, xnext.w};
            float* dst = xzs + ((t + 1) & 1) * 1088;
#pragma unroll
            for (int j = 0; j < 4; j++)
                dst[pg * 272 + (pq * 4 + j) * 17 + pb] = vv[j];
        }
        if (tid == 0) {
            while (ld_acquire(gen) < (unsigned)(t + 1)) { }
        }
        __syncthreads();
    }
}

// ---- final dense + softmax --------------------------------------------------
__global__ void fc_softmax(const float* __restrict__ fc_w,
                           const float* __restrict__ fc_b,
                           float* __restrict__ out)
{
    const int b = blockIdx.x;
    const int l = threadIdx.x;
    float a0 = 0.f, a1 = 0.f, a2 = 0.f, a3 = 0.f;
    const float* hg = &g_h[0][b][0];   // t=1023 wrote parity 0
    for (int k = l * 16; k < l * 16 + 16; k += 4) {
        float4 hv = *(const float4*)(hg + k);
        float hx[4] = {hv.x, hv.y, hv.z, hv.w};
#pragma unroll
        for (int q = 0; q < 4; q++) {
            float4 wv = *(const float4*)&fc_w[(k + q) * 4];
            a0 += hx[q] * wv.x; a1 += hx[q] * wv.y;
            a2 += hx[q] * wv.z; a3 += hx[q] * wv.w;
        }
    }
#pragma unroll
    for (int o = 16; o > 0; o >>= 1) {
        a0 += __shfl_down_sync(0xffffffffu, a0, o);
        a1 += __shfl_down_sync(0xffffffffu, a1, o);
        a2 += __shfl_down_sync(0xffffffffu, a2, o);
        a3 += __shfl_down_sync(0xffffffffu, a3, o);
    }
    if (l == 0) {
        float z0 = a0 + fc_b[0], z1 = a1 + fc_b[1];
        float z2 = a2 + fc_b[2], z3 = a3 + fc_b[3];
        float m = fmaxf(fmaxf(z0, z1), fmaxf(z2, z3));
        float e0 = __expf(z0 - m), e1 = __expf(z1 - m);
        float e2 = __expf(z2 - m), e3 = __expf(z3 - m);
        float inv = __fdividef(1.f, e0 + e1 + e2 + e3);
        out[b * 4 + 0] = e0 * inv;
        out[b * 4 + 1] = e1 * inv;
        out[b * 4 + 2] = e2 * inv;
        out[b * 4 + 3] = e3 * inv;
    }
}

// ---------------------------------------------------------------------------
extern "C" void kernel_launch(void* const* d_in, const int* in_sizes, int n_in,
                              void* d_out, int out_size)
{
    const float* tx      = (const float*)d_in[0];
    const float* kernelW = (const float*)d_in[1];
    const float* R       = (const float*)d_in[2];
    const float* bias    = (const float*)d_in[3];
    const float* fc_w    = (const float*)d_in[4];
    const float* fc_b    = (const float*)d_in[5];
    float* out           = (float*)d_out;

    cudaFuncSetAttribute(lstm_recur,
                         cudaFuncAttributeMaxDynamicSharedMemorySize, SM_BYTES);

    init_kernel<<<(2 * BATCH * UNITS + 255) / 256, 256>>>();
    prep_A<<<16384, 256>>>(tx);
    prep_W<<<256, 256>>>(kernelW);
    gemm_mma<<<dim3(16, 512), 256>>>(bias);
    lstm_recur<<<NCTA, TPB, SM_BYTES>>>(R);
    fc_softmax<<<BATCH, 32>>>(fc_w, fc_b, out);
    (void)in_sizes; (void)n_in; (void)out_size;
}

// round 17
// speedup vs baseline: 1.7397x; 1.1154x over previous
#include <cuda_runtime.h>
#include <cuda_fp16.h>
#include <cstdint>

// LSTM  B=64, T=1024, D=512, U=512, OUT=4
#define BATCH    64
#define TSTEPS   1024
#define DIN      512
#define UNITS    512
#define FOURU    2048
#define NCTA     128
#define TPB      256
#define NBG      4
#define GROUP_CTAS 32
#define NMTILE   4096
#define NKSTEP   32

// recurrence smem offsets (bytes)
#define SM_BHI   0            // f16 [64 n][520]      : 66560
#define SM_AHI   66560        // f16 [16 b][520]      : 16640
#define SM_Z     83200        // f32 [2][16 b][68]    : 8704
#define SM_XZ    91904        // f32 [2][1088]        : 8704
#define SM_BYTES 100608

__device__ float    g_xz[(size_t)BATCH * TSTEPS * FOURU];
__device__ uint4    g_Afrag[(size_t)NMTILE * NKSTEP * 32];       // hi only
__device__ uint4    g_Wfrag[(size_t)NKSTEP * 64 * 32 * 2];       // hi only
__device__ float    g_h[2][BATCH][UNITS];        // batch-major
__device__ unsigned g_arrive[NBG * 32];
__device__ unsigned g_gen[NBG * 32];

__device__ __forceinline__ float fsig(float x) {
    return __fdividef(1.f, 1.f + __expf(-x));
}
__device__ __forceinline__ float ftanh(float x) {
    return 1.f - __fdividef(2.f, __expf(2.f * x) + 1.f);
}
__device__ __forceinline__ unsigned atom_add_acqrel(unsigned* p, unsigned v) {
    unsigned old;
    asm volatile("atom.acq_rel.gpu.global.add.u32 %0, [%1], %2;"
                 : "=r"(old) : "l"(p), "r"(v) : "memory");
    return old;
}
__device__ __forceinline__ void st_release(unsigned* p, unsigned v) {
    asm volatile("st.release.gpu.global.u32 [%0], %1;" :: "l"(p), "r"(v) : "memory");
}
__device__ __forceinline__ unsigned ld_acquire(const unsigned* p) {
    unsigned v;
    asm volatile("ld.acquire.gpu.global.u32 %0, [%1];" : "=r"(v) : "l"(p) : "memory");
    return v;
}
__device__ __forceinline__ uint32_t pack_h_hi(float a, float b) {
    __half ha = __float2half_rn(a), hb = __float2half_rn(b);
    return (uint32_t)*(uint16_t*)&ha | ((uint32_t)*(uint16_t*)&hb << 16);
}
__device__ __forceinline__ uint32_t smem_u32(const void* p) {
    return (uint32_t)__cvta_generic_to_shared(p);
}

__global__ void init_kernel() {
    int i = blockIdx.x * blockDim.x + threadIdx.x;
    if (i < 2 * BATCH * UNITS) ((float*)g_h)[i] = 0.f;
    if (i < NBG * 32) { g_arrive[i] = 0u; g_gen[i] = 0u; }
}

// ---- prep A: fp16 hi fragments ----------------------------------------------
__global__ __launch_bounds__(256) void prep_A(const float* __restrict__ A) {
    int f = blockIdx.x * 256 + threadIdx.x;
    int t = f & 31, ks = (f >> 5) & 31, mt = f >> 10;
    uint32_t hi[4];
#pragma unroll
    for (int r = 0; r < 4; r++) {
        int m  = mt * 16 + (r & 1) * 8 + (t >> 2);
        int k0 = ks * 16 + ((r & 2) << 2) + ((t & 3) << 1);
        float2 av = *(const float2*)(A + (size_t)m * DIN + k0);
        hi[r] = pack_h_hi(av.x, av.y);
    }
    g_Afrag[((size_t)mt * 32 + ks) * 32 + t] = make_uint4(hi[0], hi[1], hi[2], hi[3]);
}

// ---- prep W: fp16 hi fragments ----------------------------------------------
__global__ __launch_bounds__(256) void prep_W(const float* __restrict__ W) {
    int f = blockIdx.x * 256 + threadIdx.x;     // 65536 threads
    int t = f & 31, ngrp = (f >> 5) & 63, ks = f >> 11;
    uint32_t hi[8];
#pragma unroll
    for (int nblk = 0; nblk < 4; nblk++)
#pragma unroll
        for (int reg = 0; reg < 2; reg++) {
            int k0 = ks * 16 + reg * 8 + (t & 3) * 2;
            int n  = ngrp * 32 + nblk * 8 + (t >> 2);
            float w0 = W[(size_t)k0 * FOURU + n];
            float w1 = W[(size_t)(k0 + 1) * FOURU + n];
            hi[nblk * 2 + reg] = pack_h_hi(w0, w1);
        }
    size_t wb = ((size_t)ks * 64 + ngrp) * 32 + t;
    g_Wfrag[wb * 2]     = make_uint4(hi[0], hi[1], hi[2], hi[3]);
    g_Wfrag[wb * 2 + 1] = make_uint4(hi[4], hi[5], hi[6], hi[7]);
}

#define MMA16816(c, a, b0v, b1v)                                              \
    asm volatile(                                                             \
        "mma.sync.aligned.m16n8k16.row.col.f32.f16.f16.f32 "                  \
        "{%0,%1,%2,%3}, {%4,%5,%6,%7}, {%8,%9}, {%0,%1,%2,%3};"               \
        : "+f"((c)[0]), "+f"((c)[1]), "+f"((c)[2]), "+f"((c)[3])              \
        : "r"((a).x), "r"((a).y), "r"((a).z), "r"((a).w),                     \
          "r"(b0v), "r"(b1v))

#define LDSM4(r, addr)                                                        \
    asm volatile("ldmatrix.sync.aligned.m8n8.x4.shared.b16 "                  \
                 "{%0,%1,%2,%3}, [%4];"                                       \
                 : "=r"((r).x), "=r"((r).y), "=r"((r).z), "=r"((r).w)         \
                 : "r"(addr))

// ---- xz GEMM: pure fp16 (1 mma per tile), 2 CTAs/SM ------------------------
__global__ __launch_bounds__(256, 2) void gemm_mma(const float* __restrict__ bias) {
    const int tid = threadIdx.x;
    const int t = tid & 31, wid = tid >> 5;
    const int wm = wid & 1, wn = wid >> 1;
    const int mtb = blockIdx.y * 8 + wm * 4;
    const int ngrp = blockIdx.x * 4 + wn;

    float acc[4][4][4];
#pragma unroll
    for (int mi = 0; mi < 4; mi++)
#pragma unroll
        for (int ni = 0; ni < 4; ni++)
#pragma unroll
            for (int c = 0; c < 4; c++) acc[mi][ni][c] = 0.f;

#pragma unroll 2
    for (int ks = 0; ks < NKSTEP; ks++) {
        uint4 ah[4];
#pragma unroll
        for (int mi = 0; mi < 4; mi++)
            ah[mi] = g_Afrag[((size_t)(mtb + mi) * 32 + ks) * 32 + t];
        size_t wb = ((size_t)ks * 64 + ngrp) * 32 + t;
        uint4 bh0 = g_Wfrag[wb * 2], bh1 = g_Wfrag[wb * 2 + 1];
        uint32_t bh[8] = {bh0.x, bh0.y, bh0.z, bh0.w, bh1.x, bh1.y, bh1.z, bh1.w};

#pragma unroll
        for (int mi = 0; mi < 4; mi++)
#pragma unroll
            for (int ni = 0; ni < 4; ni++)
                MMA16816(acc[mi][ni], ah[mi], bh[ni * 2], bh[ni * 2 + 1]);
    }

    const int colbase = blockIdx.x * 128 + wn * 32 + (t & 3) * 2;
    const int rowbase = blockIdx.y * 128 + wm * 64 + (t >> 2);
    float2 bv[4];
#pragma unroll
    for (int ni = 0; ni < 4; ni++)
        bv[ni] = *(const float2*)(bias + colbase + ni * 8);
#pragma unroll
    for (int mi = 0; mi < 4; mi++) {
        int r0 = rowbase + mi * 16;
#pragma unroll
        for (int ni = 0; ni < 4; ni++) {
            int col = colbase + ni * 8;
            float2 o0 = make_float2(acc[mi][ni][0] + bv[ni].x,
                                    acc[mi][ni][1] + bv[ni].y);
            float2 o1 = make_float2(acc[mi][ni][2] + bv[ni].x,
                                    acc[mi][ni][3] + bv[ni].y);
            __stcs((float2*)(g_xz + (size_t)r0 * FOURU + col), o0);
            __stcs((float2*)(g_xz + (size_t)(r0 + 8) * FOURU + col), o1);
        }
    }
}

// ---- persistent LSTM recurrence: pure fp16 (2 mma per k-tile) --------------
__global__ __launch_bounds__(TPB, 1) void lstm_recur(const float* __restrict__ R)
{
    extern __shared__ char smc[];
    __half* Bhi = (__half*)(smc + SM_BHI);
    uint32_t* AhiW = (uint32_t*)(smc + SM_AHI);
    float* zbuf = (float*)(smc + SM_Z);       // [2][16][68]
    float* xzs  = (float*)(smc + SM_XZ);

    const int tid = threadIdx.x;
    const int wid = tid >> 5, lane = tid & 31;
    const int ug = blockIdx.x >> 2, bg = blockIdx.x & 3;
    const int u0 = ug * 16, b0 = bg * 16;

    // ---- build B (R slice) once: B[n][k] = R[k][g*512+u0+j], n = g*16+j ----
    for (int i = tid; i < 64 * 512; i += TPB) {
        int k = i & 511, n = i >> 9;
        int g = n >> 4, j = n & 15;
        float v = R[(size_t)k * FOURU + g * UNITS + u0 + j];
        Bhi[n * 520 + k] = __float2half_rn(v);
    }

    // ---- xz staging map: thread -> (pb, pg, pq) ----------------------------
    const int pb = tid >> 4, pg = (tid >> 2) & 3, pq = tid & 3;
    const float* xz_thread = g_xz + (size_t)(b0 + pb) * TSTEPS * FOURU
                             + pg * UNITS + u0 + pq * 4;
    {
        float4 v = __ldcs((const float4*)xz_thread);
        float vv[4] = {v.x, v.y, v.z, v.w};
#pragma unroll
        for (int j = 0; j < 4; j++)
            xzs[pg * 272 + (pq * 4 + j) * 17 + pb] = vv[j];
    }
    __syncthreads();

    // ---- lane-invariant LDSM addresses -------------------------------------
    const int khalf = wid >> 2, npair = wid & 3;
    const int aRow = (lane & 7) + ((lane >> 3) & 1) * 8;
    const int aKof = ((lane >> 4) & 1) * 16;            // bytes
    const uint32_t aHiAddr = smem_u32(smc + SM_AHI) + aRow * 1040 + aKof;
    const int bRow = npair * 16 + ((lane >> 4) & 1) * 8 + (lane & 7);
    const int bKof = ((lane >> 3) & 1) * 16;
    const uint32_t bHiAddr = smem_u32(smc + SM_BHI) + bRow * 1040 + bKof;

    // ---- preload this warp's B-hi fragments into registers (time-invariant)
    uint4 Bh[16];
#pragma unroll
    for (int i = 0; i < 16; i++)
        LDSM4(Bh[i], bHiAddr + (khalf * 16 + i) * 32);

    // A-staging map: b = tid>>4, 8 chunks of 4 floats at u = (tid&15)*4+q*64
    const int sb = tid >> 4, su = (tid & 15) * 4;
    // gates map (coalesced h writeback): b = tid>>4, u = tid&15
    const int b_l = tid >> 4, j_l = tid & 15;

    unsigned* arrive = &g_arrive[bg * 32];
    unsigned* gen    = &g_gen[bg * 32];

    float c_state = 0.f;

    for (int t = 0; t < TSTEPS; t++) {
        const int par = t & 1;
        float4 xnext = make_float4(0.f, 0.f, 0.f, 0.f);
        if (t + 1 < TSTEPS)
            xnext = __ldcs((const float4*)(xz_thread + (size_t)(t + 1) * FOURU));

        // ---- stage A = h(t)[16 b][512 k] as fp16 ----
        const float* hsrc = &g_h[par][b0 + sb][0];
#pragma unroll
        for (int q = 0; q < 8; q++) {
            int u = su + q * 64;
            float4 v = __ldcg((const float4*)(hsrc + u));
            uint32_t h01, h23;
            asm("cvt.rn.f16x2.f32 %0, %1, %2;" : "=r"(h01) : "f"(v.y), "f"(v.x));
            asm("cvt.rn.f16x2.f32 %0, %1, %2;" : "=r"(h23) : "f"(v.w), "f"(v.z));
            int w = sb * 260 + u / 2;
            AhiW[w] = h01; AhiW[w + 1] = h23;
        }
        __syncthreads();

        // ---- MMA: n-tiles {2*npair, 2*npair+1}, k-half khalf ----
        float acc0[4] = {0.f, 0.f, 0.f, 0.f};
        float acc1[4] = {0.f, 0.f, 0.f, 0.f};
#pragma unroll
        for (int i = 0; i < 16; i++) {
            uint4 ah;
            LDSM4(ah, aHiAddr + (khalf * 16 + i) * 32);
            MMA16816(acc0, ah, Bh[i].x, Bh[i].y);
            MMA16816(acc1, ah, Bh[i].z, Bh[i].w);
        }

        // ---- both halves write partial z to their own buffer ----
        {
            float* zb = zbuf + khalf * 1088;
            int ra = lane >> 2, cb = (lane & 3) * 2;
            int n0 = npair * 16 + cb, n1 = npair * 16 + 8 + cb;
            *(float2*)&zb[ra * 68 + n0]       = make_float2(acc0[0], acc0[1]);
            *(float2*)&zb[(ra + 8) * 68 + n0] = make_float2(acc0[2], acc0[3]);
            *(float2*)&zb[ra * 68 + n1]       = make_float2(acc1[0], acc1[1]);
            *(float2*)&zb[(ra + 8) * 68 + n1] = make_float2(acc1[2], acc1[3]);
        }
        __syncthreads();

        // ---- gates: thread (b_l = tid>>4, j_l = tid&15) ----
        {
            const float* z0 = zbuf + b_l * 68 + j_l;
            const float* z1 = zbuf + 1088 + b_l * 68 + j_l;
            const float* xb = xzs + par * 1088 + j_l * 17 + b_l;
            float zv1 = z0[0]  + z1[0]  + xb[0];
            float zv2 = z0[16] + z1[16] + xb[272];
            float zv3 = z0[32] + z1[32] + xb[544];
            float zv4 = z0[48] + z1[48] + xb[816];
            float v1 = ftanh(zv1);
            float v2 = fsig(zv2);
            float v3 = fsig(zv3);
            float v4 = fsig(zv4);
            c_state = v1 * v2 + v3 * c_state;
            float hnew = v4 * ftanh(c_state);
            __stcg(&g_h[par ^ 1][b0 + b_l][u0 + j_l], hnew);
        }

        // ---- barrier: arrive early, stage xz, poll ----
        __syncthreads();
        if (tid == 0) {
            unsigned prev = atom_add_acqrel(arrive, 1u);
            if ((prev & 31u) == 31u)
                st_release(gen, (unsigned)(t + 1));
        }
        if (t + 1 < TSTEPS) {
            float vv[4] = {xnext.x, xnext.y, xnext.z, xnext.w};
            float* dst = xzs + ((t + 1) & 1) * 1088;
#pragma unroll
            for (int j = 0; j < 4; j++)
                dst[pg * 272 + (pq * 4 + j) * 17 + pb] = vv[j];
        }
        if (tid == 0) {
            while (ld_acquire(gen) < (unsigned)(t + 1)) { }
        }
        __syncthreads();
    }
}

// ---- final dense + softmax --------------------------------------------------
__global__ void fc_softmax(const float* __restrict__ fc_w,
                           const float* __restrict__ fc_b,
                           float* __restrict__ out)
{
    const int b = blockIdx.x;
    const int l = threadIdx.x;
    float a0 = 0.f, a1 = 0.f, a2 = 0.f, a3 = 0.f;
    const float* hg = &g_h[0][b][0];   // t=1023 wrote parity 0
    for (int k = l * 16; k < l * 16 + 16; k += 4) {
        float4 hv = *(const float4*)(hg + k);
        float hx[4] = {hv.x, hv.y, hv.z, hv.w};
#pragma unroll
        for (int q = 0; q < 4; q++) {
            float4 wv = *(const float4*)&fc_w[(k + q) * 4];
            a0 += hx[q] * wv.x; a1 += hx[q] * wv.y;
            a2 += hx[q] * wv.z; a3 += hx[q] * wv.w;
        }
    }
#pragma unroll
    for (int o = 16; o > 0; o >>= 1) {
        a0 += __shfl_down_sync(0xffffffffu, a0, o);
        a1 += __shfl_down_sync(0xffffffffu, a1, o);
        a2 += __shfl_down_sync(0xffffffffu, a2, o);
        a3 += __shfl_down_sync(0xffffffffu, a3, o);
    }
    if (l == 0) {
        float z0 = a0 + fc_b[0], z1 = a1 + fc_b[1];
        float z2 = a2 + fc_b[2], z3 = a3 + fc_b[3];
        float m = fmaxf(fmaxf(z0, z1), fmaxf(z2, z3));
        float e0 = __expf(z0 - m), e1 = __expf(z1 - m);
        float e2 = __expf(z2 - m), e3 = __expf(z3 - m);
        float inv = __fdividef(1.f, e0 + e1 + e2 + e3);
        out[b * 4 + 0] = e0 * inv;
        out[b * 4 + 1] = e1 * inv;
        out[b * 4 + 2] = e2 * inv;
        out[b * 4 + 3] = e3 * inv;
    }
}

// ---------------------------------------------------------------------------
extern "C" void kernel_launch(void* const* d_in, const int* in_sizes, int n_in,
                              void* d_out, int out_size)
{
    const float* tx      = (const float*)d_in[0];
    const float* kernelW = (const float*)d_in[1];
    const float* R       = (const float*)d_in[2];
    const float* bias    = (const float*)d_in[3];
    const float* fc_w    = (const float*)d_in[4];
    const float* fc_b    = (const float*)d_in[5];
    float* out           = (float*)d_out;

    cudaFuncSetAttribute(lstm_recur,
                         cudaFuncAttributeMaxDynamicSharedMemorySize, SM_BYTES);

    init_kernel<<<(2 * BATCH * UNITS + 255) / 256, 256>>>();
    prep_A<<<16384, 256>>>(tx);
    prep_W<<<256, 256>>>(kernelW);
    gemm_mma<<<dim3(16, 512), 256>>>(bias);
    lstm_recur<<<NCTA, TPB, SM_BYTES>>>(R);
    fc_softmax<<<BATCH, 32>>>(fc_w, fc_b, out);
    (void)in_sizes; (void)n_in; (void)out_size;
}